// round 3
// baseline (speedup 1.0000x reference)
#include <cuda_runtime.h>
#include <math.h>
#include <stdint.h>

#define BB 4
#define SS 1024
#define DD 1024
#define HH 16
#define HDIM 64
#define NEGV -10000000000.0f

// Scratch (module-load allocated; no runtime allocs)
__device__ float g_Q[BB*HH*SS*HDIM];
__device__ float g_K[BB*HH*SS*HDIM];
__device__ float g_V[BB*HH*SS*HDIM];
__device__ float g_attn[BB*SS*DD];

// ---------------------------------------------------------------------------
// tf32 helpers
// ---------------------------------------------------------------------------
__device__ __forceinline__ uint32_t f2tf(float f) {
    uint32_t u;
    asm("cvt.rna.tf32.f32 %0, %1;" : "=r"(u) : "f"(f));
    return u;
}

__device__ __forceinline__ void mma8(float* c, const uint32_t* a, const uint32_t* b) {
    asm volatile(
        "mma.sync.aligned.m16n8k8.row.col.f32.tf32.tf32.f32 "
        "{%0,%1,%2,%3}, {%4,%5,%6,%7}, {%8,%9}, {%0,%1,%2,%3};"
        : "+f"(c[0]), "+f"(c[1]), "+f"(c[2]), "+f"(c[3])
        : "r"(a[0]), "r"(a[1]), "r"(a[2]), "r"(a[3]), "r"(b[0]), "r"(b[1]));
}

// ---------------------------------------------------------------------------
// tf32 GEMM: C[4096,1024] = X[4096,1024] @ W + bias
// MODE 0: W is [H][D][HD] (proj weights), output scattered to [B,H,S,64]
// MODE 1: W is [D][D] (Wo), output row-major [4096][1024]
// 128x128x32 tiles, 8 warps of 64x32, m16n8k8 tf32 fragments.
// Smem holds tf32-converted values in a k-permuted layout:
//   col(k) = (k>>3)*8 + 2*(k&3) + ((k>>2)&1)
// so fragment k-pairs (q, q+4) are one LDS.64; row stride 40 -> conflict-free.
// ---------------------------------------------------------------------------
template<int MODE>
__device__ __forceinline__ void gemm_tf32(const float* __restrict__ X,
                                          const float* __restrict__ W,
                                          const float* __restrict__ bias,
                                          float* __restrict__ out)
{
    __shared__ uint32_t As[128][40];
    __shared__ uint32_t Bs[128][40];

    const int tid  = threadIdx.x;
    const int lane = tid & 31;
    const int w    = tid >> 5;
    const int g    = lane >> 2;
    const int q    = lane & 3;
    const int wm   = (w >> 2) * 64;   // warp row offset (0/64)
    const int wn   = (w & 3) * 32;    // warp col offset (0/32/64/96)
    const int m0   = blockIdx.y * 128;
    const int n0   = blockIdx.x * 128;

    float acc[4][4][4];
    #pragma unroll
    for (int i = 0; i < 4; i++)
        #pragma unroll
        for (int j = 0; j < 4; j++)
            #pragma unroll
            for (int r = 0; r < 4; r++) acc[i][j][r] = 0.f;

    float4 aR[4], bR[4];

    // ---- global load of tile kt into registers ----
    auto load_tile = [&](int kt) {
        #pragma unroll
        for (int i = 0; i < 4; i++) {
            const int idx = tid + i * 256;
            const int row = idx >> 3, c = idx & 7;
            aR[i] = *(const float4*)(X + (size_t)(m0 + row) * DD + kt * 32 + c * 4);
        }
        #pragma unroll
        for (int i = 0; i < 4; i++) {
            const int idx = tid + i * 256;
            const int kk = idx >> 5, nc = (idx & 31) * 4;
            const float* p;
            if (MODE == 0) {
                const int n = n0 + nc;
                p = W + (size_t)(n >> 6) * (DD * HDIM) + (size_t)(kt * 32 + kk) * HDIM + (n & 63);
            } else {
                p = W + (size_t)(kt * 32 + kk) * DD + n0 + nc;
            }
            bR[i] = *(const float4*)p;
        }
    };

    // ---- regs -> smem (cvt.rna + k-permute) ----
    auto store_tile = [&]() {
        #pragma unroll
        for (int i = 0; i < 4; i++) {
            const int idx = tid + i * 256;
            const int row = idx >> 3, c = idx & 7;
            const int base = (c >> 1) * 8 + (c & 1);   // col for j=0; +2 per j
            As[row][base + 0] = f2tf(aR[i].x);
            As[row][base + 2] = f2tf(aR[i].y);
            As[row][base + 4] = f2tf(aR[i].z);
            As[row][base + 6] = f2tf(aR[i].w);
        }
        #pragma unroll
        for (int i = 0; i < 4; i++) {
            const int idx = tid + i * 256;
            const int kk = idx >> 5, nc = (idx & 31) * 4;
            const int col = (kk >> 3) * 8 + ((kk & 3) << 1) + ((kk >> 2) & 1);
            Bs[nc + 0][col] = f2tf(bR[i].x);
            Bs[nc + 1][col] = f2tf(bR[i].y);
            Bs[nc + 2][col] = f2tf(bR[i].z);
            Bs[nc + 3][col] = f2tf(bR[i].w);
        }
    };

    auto compute = [&]() {
        #pragma unroll
        for (int ks = 0; ks < 4; ks++) {
            uint32_t af[4][4], bf[4][2];
            #pragma unroll
            for (int mf = 0; mf < 4; mf++) {
                const int m = wm + mf * 16 + g;
                const uint2 t0 = *(const uint2*)&As[m][ks * 8 + 2 * q];
                const uint2 t1 = *(const uint2*)&As[m + 8][ks * 8 + 2 * q];
                af[mf][0] = t0.x; af[mf][2] = t0.y;
                af[mf][1] = t1.x; af[mf][3] = t1.y;
            }
            #pragma unroll
            for (int nf = 0; nf < 4; nf++) {
                const int n = wn + nf * 8 + g;
                const uint2 t = *(const uint2*)&Bs[n][ks * 8 + 2 * q];
                bf[nf][0] = t.x; bf[nf][1] = t.y;
            }
            #pragma unroll
            for (int mf = 0; mf < 4; mf++)
                #pragma unroll
                for (int nf = 0; nf < 4; nf++)
                    mma8(acc[mf][nf], af[mf], bf[nf]);
        }
    };

    load_tile(0);
    store_tile();
    __syncthreads();

    for (int kt = 0; kt < 32; kt++) {
        if (kt < 31) load_tile(kt + 1);
        compute();
        __syncthreads();
        if (kt < 31) {
            store_tile();
            __syncthreads();
        }
    }

    // ---- epilogue: bias + store ----
    #pragma unroll
    for (int mf = 0; mf < 4; mf++) {
        const int m = m0 + wm + mf * 16 + g;
        #pragma unroll
        for (int nf = 0; nf < 4; nf++) {
            const int n = n0 + wn + nf * 8 + 2 * q;
            const float b0v = bias[n], b1v = bias[n + 1];
            float2 v0 = make_float2(acc[mf][nf][0] + b0v, acc[mf][nf][1] + b1v);
            float2 v1 = make_float2(acc[mf][nf][2] + b0v, acc[mf][nf][3] + b1v);
            if (MODE == 0) {
                const int b_ = m >> 10, s_ = m & (SS - 1);
                const int h_ = n >> 6, e_ = n & 63;
                float* base = out + ((size_t)(b_ * HH + h_) * SS + s_) * HDIM + e_;
                *(float2*)base = v0;
                *(float2*)(base + 8 * HDIM) = v1;   // row m+8
            } else {
                *(float2*)(out + (size_t)m * DD + n) = v0;
                *(float2*)(out + (size_t)(m + 8) * DD + n) = v1;
            }
        }
    }
}

__global__ __launch_bounds__(256)
void proj_kernel(const float* __restrict__ Xq, const float* __restrict__ Xk,
                 const float* __restrict__ Xv,
                 const float* __restrict__ Wq, const float* __restrict__ Wk,
                 const float* __restrict__ Wv,
                 const float* __restrict__ bq, const float* __restrict__ bk,
                 const float* __restrict__ bv)
{
    const float *X, *W, *bias;
    float* out;
    if (blockIdx.z == 0)      { X = Xq; W = Wq; bias = bq; out = g_Q; }
    else if (blockIdx.z == 1) { X = Xk; W = Wk; bias = bk; out = g_K; }
    else                      { X = Xv; W = Wv; bias = bv; out = g_V; }
    gemm_tf32<0>(X, W, bias, out);
}

__global__ __launch_bounds__(256)
void outproj_kernel(const float* __restrict__ Wo, const float* __restrict__ bo,
                    float* __restrict__ out)
{
    gemm_tf32<1>(g_attn, Wo, bo, out);
}

// ---------------------------------------------------------------------------
// Flash-style attention per (b,h), 64 query rows per block, KV tiles of 32.
// Reproduces reference masking exactly: masked logits get +NEG (counted in
// the softmax denominator), numerators are zeroed (p*m) via s' > -5e9 test.
// (unchanged from R1 — passes at 1e-6; converting to mma is next round)
// ---------------------------------------------------------------------------
__global__ __launch_bounds__(256, 2)
void attn_kernel(const int* __restrict__ mask)
{
    const int bh = blockIdx.y;
    const int b_ = bh >> 4;
    const int h_ = bh & 15;
    const int q0 = blockIdx.x * 64;

    const float* Qp = g_Q + (size_t)bh * SS * HDIM;
    const float* Kp = g_K + (size_t)bh * SS * HDIM;
    const float* Vp = g_V + (size_t)bh * SS * HDIM;

    __shared__ float Qs[64][64];
    __shared__ float Ks[32][68];
    __shared__ float Vs[32][64];
    __shared__ float Ps[64][33];
    __shared__ float rowAlpha[64];
    __shared__ float rowInv[64];

    const int tid = threadIdx.x;
    const int tx = tid & 15, ty = tid >> 4;
    const int r0 = ty * 4;
    const int e0 = tx * 4;

    #pragma unroll
    for (int i = 0; i < 4; i++) {
        const int idx = tid + i * 256;
        const int row = idx >> 4, c4 = (idx & 15) * 4;
        *(float4*)&Qs[row][c4] = *(const float4*)(Qp + (size_t)(q0 + row) * HDIM + c4);
    }

    float O[4][4];
    #pragma unroll
    for (int i = 0; i < 4; i++)
        #pragma unroll
        for (int j = 0; j < 4; j++) O[i][j] = 0.f;

    float rM = -1e30f, rL = 0.f;
    const float scale = 0.03125f;

    for (int t0 = 0; t0 < SS; t0 += 32) {
        #pragma unroll
        for (int i = 0; i < 2; i++) {
            const int idx = tid + i * 256;
            const int row = idx >> 4, c4 = (idx & 15) * 4;
            *(float4*)&Ks[row][c4] = *(const float4*)(Kp + (size_t)(t0 + row) * HDIM + c4);
            *(float4*)&Vs[row][c4] = *(const float4*)(Vp + (size_t)(t0 + row) * HDIM + c4);
        }
        __syncthreads();

        float sa[4][2];
        #pragma unroll
        for (int i = 0; i < 4; i++) { sa[i][0] = 0.f; sa[i][1] = 0.f; }
        #pragma unroll
        for (int e = 0; e < 64; e += 4) {
            const float4 k0v = *(const float4*)&Ks[tx][e];
            const float4 k1v = *(const float4*)&Ks[tx + 16][e];
            #pragma unroll
            for (int i = 0; i < 4; i++) {
                const float4 qv = *(const float4*)&Qs[r0 + i][e];
                sa[i][0] += qv.x * k0v.x + qv.y * k0v.y + qv.z * k0v.z + qv.w * k0v.w;
                sa[i][1] += qv.x * k1v.x + qv.y * k1v.y + qv.z * k1v.z + qv.w * k1v.w;
            }
        }
        #pragma unroll
        for (int i = 0; i < 4; i++) {
            const int* mrow = mask + (size_t)(b_ * SS + q0 + r0 + i) * SS + t0;
            Ps[r0 + i][tx]      = sa[i][0] * scale + (mrow[tx]      ? 0.f : NEGV);
            Ps[r0 + i][tx + 16] = sa[i][1] * scale + (mrow[tx + 16] ? 0.f : NEGV);
        }
        __syncthreads();

        if (tid < 64) {
            float m = rM;
            #pragma unroll
            for (int t = 0; t < 32; t++) m = fmaxf(m, Ps[tid][t]);
            const float alpha = __expf(rM - m);
            float lsum = 0.f;
            #pragma unroll
            for (int t = 0; t < 32; t++) {
                const float v = Ps[tid][t];
                const float p = __expf(v - m);
                lsum += p;
                Ps[tid][t] = (v > -5.0e9f) ? p : 0.f;
            }
            rL = rL * alpha + lsum;
            rM = m;
            rowAlpha[tid] = alpha;
        }
        __syncthreads();

        #pragma unroll
        for (int i = 0; i < 4; i++) {
            const float a = rowAlpha[r0 + i];
            #pragma unroll
            for (int j = 0; j < 4; j++) O[i][j] *= a;
        }
        #pragma unroll
        for (int t = 0; t < 32; t++) {
            const float4 vv = *(const float4*)&Vs[t][e0];
            #pragma unroll
            for (int i = 0; i < 4; i++) {
                const float p = Ps[r0 + i][t];
                O[i][0] += p * vv.x;
                O[i][1] += p * vv.y;
                O[i][2] += p * vv.z;
                O[i][3] += p * vv.w;
            }
        }
        __syncthreads();
    }

    if (tid < 64) rowInv[tid] = 1.f / rL;
    __syncthreads();

    #pragma unroll
    for (int i = 0; i < 4; i++) {
        const float inv = rowInv[r0 + i];
        float4 o;
        o.x = O[i][0] * inv; o.y = O[i][1] * inv;
        o.z = O[i][2] * inv; o.w = O[i][3] * inv;
        *(float4*)(g_attn + (size_t)(b_ * SS + q0 + r0 + i) * DD + h_ * HDIM + e0) = o;
    }
}

// ---------------------------------------------------------------------------
extern "C" void kernel_launch(void* const* d_in, const int* in_sizes, int n_in,
                              void* d_out, int out_size)
{
    const float* q    = (const float*)d_in[0];
    const float* k    = (const float*)d_in[1];
    const float* v    = (const float*)d_in[2];
    const int*   mask = (const int*)  d_in[3];
    const float* Wq   = (const float*)d_in[4];
    const float* bq   = (const float*)d_in[5];
    const float* Wk   = (const float*)d_in[6];
    const float* bk   = (const float*)d_in[7];
    const float* Wv   = (const float*)d_in[8];
    const float* bv   = (const float*)d_in[9];
    const float* Wo   = (const float*)d_in[10];
    const float* bo   = (const float*)d_in[11];
    float* out = (float*)d_out;

    dim3 g1(8, 32, 3);                 // N/128, M/128, {Q,K,V}
    proj_kernel<<<g1, 256>>>(q, k, v, Wq, Wk, Wv, bq, bk, bv);

    dim3 g2(16, 64);                   // S/64 query tiles, B*H
    attn_kernel<<<g2, 256>>>(mask);

    dim3 g3(8, 32);                    // N/128, M/128
    outproj_kernel<<<g3, 256>>>(Wo, bo, out);
}

// round 5
// speedup vs baseline: 1.6785x; 1.6785x over previous
#include <cuda_runtime.h>
#include <math.h>
#include <stdint.h>

#define BB 4
#define SS 1024
#define DD 1024
#define HH 16
#define HDIM 64
#define NEGV -10000000000.0f

// Scratch (module-load allocated; no runtime allocs)
__device__ float g_Q[BB*HH*SS*HDIM];
__device__ float g_K[BB*HH*SS*HDIM];
__device__ float g_V[BB*HH*SS*HDIM];
__device__ float g_attn[BB*SS*DD];

// ---------------------------------------------------------------------------
// tf32 helpers
// ---------------------------------------------------------------------------
__device__ __forceinline__ uint32_t f2tf(float f) {
    uint32_t u;
    asm("cvt.rna.tf32.f32 %0, %1;" : "=r"(u) : "f"(f));
    return u;
}

__device__ __forceinline__ void mma8(float* c, const uint32_t* a, const uint32_t* b) {
    asm volatile(
        "mma.sync.aligned.m16n8k8.row.col.f32.tf32.tf32.f32 "
        "{%0,%1,%2,%3}, {%4,%5,%6,%7}, {%8,%9}, {%0,%1,%2,%3};"
        : "+f"(c[0]), "+f"(c[1]), "+f"(c[2]), "+f"(c[3])
        : "r"(a[0]), "r"(a[1]), "r"(a[2]), "r"(a[3]), "r"(b[0]), "r"(b[1]));
}

// ---------------------------------------------------------------------------
// tf32 GEMM: C[4096,1024] = X[4096,1024] @ W + bias
// MODE 0: W is [H][D][HD] (proj weights), output scattered to [B,H,S,64]
// MODE 1: W is [D][D] (Wo), output row-major [4096][1024]
//
// 128x128x16 tiles, double-buffered smem, ONE __syncthreads per k-step.
// 8 warps of 64x32, m16n8k8 tf32 fragments.
//
// A smem: [128][ASTR=24], k-permuted cols col(k)=(k>>3)*8+2*(k&3)+((k>>2)&1)
//   -> fragment (q,q+4) pair is one LDS.64; stride 24 == conflict-free loads.
// B smem: TRANSPOSED [16][BSTR=136] (k-major, n contiguous)
//   -> stores are coalesced STS.128 (conflict-free);
//   -> fragment loads LDS.32 with banks 8q+g: conflict-free.
// ---------------------------------------------------------------------------
#define ASTR 24
#define BSTR 136

template<int MODE>
__device__ __forceinline__ void gemm_tf32(const float* __restrict__ X,
                                          const float* __restrict__ W,
                                          const float* __restrict__ bias,
                                          float* __restrict__ out)
{
    __shared__ uint32_t As[2][128][ASTR];
    __shared__ uint32_t Bs[2][16][BSTR];

    const int tid  = threadIdx.x;
    const int lane = tid & 31;
    const int w    = tid >> 5;
    const int g    = lane >> 2;
    const int q    = lane & 3;
    const int wm   = (w >> 2) * 64;   // warp row offset (0/64)
    const int wn   = (w & 3) * 32;    // warp col offset (0/32/64/96)
    const int m0   = blockIdx.y * 128;
    const int n0   = blockIdx.x * 128;

    // A load mapping: 128x16 floats = 512 float4; thread covers idx, idx+256
    const int aRow = tid >> 2;            // 0..63 (+64 for second)
    const int aC4  = (tid & 3) * 4;       // k offset within tile
    const int aBase = ((aC4 >> 3) * 8) + ((aC4 >> 2) & 1); // k-permute base
    // B load mapping: 16x128 floats = 512 float4
    const int bKK = tid >> 5;             // 0..7 (+8 for second)
    const int bNC = (tid & 31) * 4;       // n offset

    float acc[4][4][4];
    #pragma unroll
    for (int i = 0; i < 4; i++)
        #pragma unroll
        for (int j = 0; j < 4; j++)
            #pragma unroll
            for (int r = 0; r < 4; r++) acc[i][j][r] = 0.f;

    float4 aR[2], bR[2];

    auto load_tile = [&](int kt) {
        #pragma unroll
        for (int i = 0; i < 2; i++)
            aR[i] = *(const float4*)(X + (size_t)(m0 + aRow + i * 64) * DD + kt * 16 + aC4);
        #pragma unroll
        for (int i = 0; i < 2; i++) {
            const int kk = bKK + i * 8;
            const float* p;
            if (MODE == 0) {
                const int n = n0 + bNC;
                p = W + (size_t)(n >> 6) * (DD * HDIM) + (size_t)(kt * 16 + kk) * HDIM + (n & 63);
            } else {
                p = W + (size_t)(kt * 16 + kk) * DD + n0 + bNC;
            }
            bR[i] = *(const float4*)p;
        }
    };

    auto store_tile = [&](int buf) {
        #pragma unroll
        for (int i = 0; i < 2; i++) {
            uint32_t* r = &As[buf][aRow + i * 64][0];
            r[aBase + 0] = f2tf(aR[i].x);
            r[aBase + 2] = f2tf(aR[i].y);
            r[aBase + 4] = f2tf(aR[i].z);
            r[aBase + 6] = f2tf(aR[i].w);
        }
        #pragma unroll
        for (int i = 0; i < 2; i++) {
            uint4 v;
            v.x = f2tf(bR[i].x); v.y = f2tf(bR[i].y);
            v.z = f2tf(bR[i].z); v.w = f2tf(bR[i].w);
            *(uint4*)&Bs[buf][bKK + i * 8][bNC] = v;     // STS.128, coalesced
        }
    };

    auto compute = [&](int buf) {
        #pragma unroll
        for (int ks = 0; ks < 2; ks++) {
            uint32_t af[4][4], bf[4][2];
            #pragma unroll
            for (int mf = 0; mf < 4; mf++) {
                const int m = wm + mf * 16 + g;
                const uint2 t0 = *(const uint2*)&As[buf][m][ks * 8 + 2 * q];
                const uint2 t1 = *(const uint2*)&As[buf][m + 8][ks * 8 + 2 * q];
                af[mf][0] = t0.x; af[mf][2] = t0.y;
                af[mf][1] = t1.x; af[mf][3] = t1.y;
            }
            #pragma unroll
            for (int nf = 0; nf < 4; nf++) {
                const int n = wn + nf * 8 + g;
                bf[nf][0] = Bs[buf][ks * 8 + q][n];
                bf[nf][1] = Bs[buf][ks * 8 + q + 4][n];
            }
            #pragma unroll
            for (int mf = 0; mf < 4; mf++)
                #pragma unroll
                for (int nf = 0; nf < 4; nf++)
                    mma8(acc[mf][nf], af[mf], bf[nf]);
        }
    };

    load_tile(0);
    store_tile(0);
    __syncthreads();

    int buf = 0;
    for (int kt = 0; kt < 64; kt++) {
        if (kt < 63) load_tile(kt + 1);
        compute(buf);
        if (kt < 63) store_tile(buf ^ 1);
        __syncthreads();
        buf ^= 1;
    }

    // ---- epilogue: bias + store ----
    #pragma unroll
    for (int mf = 0; mf < 4; mf++) {
        const int m = m0 + wm + mf * 16 + g;
        #pragma unroll
        for (int nf = 0; nf < 4; nf++) {
            const int n = n0 + wn + nf * 8 + 2 * q;
            const float b0v = bias[n], b1v = bias[n + 1];
            float2 v0 = make_float2(acc[mf][nf][0] + b0v, acc[mf][nf][1] + b1v);
            float2 v1 = make_float2(acc[mf][nf][2] + b0v, acc[mf][nf][3] + b1v);
            if (MODE == 0) {
                const int b_ = m >> 10, s_ = m & (SS - 1);
                const int h_ = n >> 6, e_ = n & 63;
                float* base = out + ((size_t)(b_ * HH + h_) * SS + s_) * HDIM + e_;
                *(float2*)base = v0;
                *(float2*)(base + 8 * HDIM) = v1;   // row m+8
            } else {
                *(float2*)(out + (size_t)m * DD + n) = v0;
                *(float2*)(out + (size_t)(m + 8) * DD + n) = v1;
            }
        }
    }
}

__global__ __launch_bounds__(256, 2)
void proj_kernel(const float* __restrict__ Xq, const float* __restrict__ Xk,
                 const float* __restrict__ Xv,
                 const float* __restrict__ Wq, const float* __restrict__ Wk,
                 const float* __restrict__ Wv,
                 const float* __restrict__ bq, const float* __restrict__ bk,
                 const float* __restrict__ bv)
{
    const float *X, *W, *bias;
    float* out;
    if (blockIdx.z == 0)      { X = Xq; W = Wq; bias = bq; out = g_Q; }
    else if (blockIdx.z == 1) { X = Xk; W = Wk; bias = bk; out = g_K; }
    else                      { X = Xv; W = Wv; bias = bv; out = g_V; }
    gemm_tf32<0>(X, W, bias, out);
}

__global__ __launch_bounds__(256, 2)
void outproj_kernel(const float* __restrict__ Wo, const float* __restrict__ bo,
                    float* __restrict__ out)
{
    gemm_tf32<1>(g_attn, Wo, bo, out);
}

// ---------------------------------------------------------------------------
// Flash-style attention per (b,h), 64 query rows per block, KV tiles of 32.
// Reproduces reference masking exactly: masked logits get +NEG (counted in
// the softmax denominator), numerators are zeroed (p*m) via s' > -5e9 test.
// (unchanged — at the fp32 FFMA floor; converting to mma is next round)
// ---------------------------------------------------------------------------
__global__ __launch_bounds__(256, 2)
void attn_kernel(const int* __restrict__ mask)
{
    const int bh = blockIdx.y;
    const int b_ = bh >> 4;
    const int h_ = bh & 15;
    const int q0 = blockIdx.x * 64;

    const float* Qp = g_Q + (size_t)bh * SS * HDIM;
    const float* Kp = g_K + (size_t)bh * SS * HDIM;
    const float* Vp = g_V + (size_t)bh * SS * HDIM;

    __shared__ float Qs[64][64];
    __shared__ float Ks[32][68];
    __shared__ float Vs[32][64];
    __shared__ float Ps[64][33];
    __shared__ float rowAlpha[64];
    __shared__ float rowInv[64];

    const int tid = threadIdx.x;
    const int tx = tid & 15, ty = tid >> 4;
    const int r0 = ty * 4;
    const int e0 = tx * 4;

    #pragma unroll
    for (int i = 0; i < 4; i++) {
        const int idx = tid + i * 256;
        const int row = idx >> 4, c4 = (idx & 15) * 4;
        *(float4*)&Qs[row][c4] = *(const float4*)(Qp + (size_t)(q0 + row) * HDIM + c4);
    }

    float O[4][4];
    #pragma unroll
    for (int i = 0; i < 4; i++)
        #pragma unroll
        for (int j = 0; j < 4; j++) O[i][j] = 0.f;

    float rM = -1e30f, rL = 0.f;
    const float scale = 0.03125f;

    for (int t0 = 0; t0 < SS; t0 += 32) {
        #pragma unroll
        for (int i = 0; i < 2; i++) {
            const int idx = tid + i * 256;
            const int row = idx >> 4, c4 = (idx & 15) * 4;
            *(float4*)&Ks[row][c4] = *(const float4*)(Kp + (size_t)(t0 + row) * HDIM + c4);
            *(float4*)&Vs[row][c4] = *(const float4*)(Vp + (size_t)(t0 + row) * HDIM + c4);
        }
        __syncthreads();

        float sa[4][2];
        #pragma unroll
        for (int i = 0; i < 4; i++) { sa[i][0] = 0.f; sa[i][1] = 0.f; }
        #pragma unroll
        for (int e = 0; e < 64; e += 4) {
            const float4 k0v = *(const float4*)&Ks[tx][e];
            const float4 k1v = *(const float4*)&Ks[tx + 16][e];
            #pragma unroll
            for (int i = 0; i < 4; i++) {
                const float4 qv = *(const float4*)&Qs[r0 + i][e];
                sa[i][0] += qv.x * k0v.x + qv.y * k0v.y + qv.z * k0v.z + qv.w * k0v.w;
                sa[i][1] += qv.x * k1v.x + qv.y * k1v.y + qv.z * k1v.z + qv.w * k1v.w;
            }
        }
        #pragma unroll
        for (int i = 0; i < 4; i++) {
            const int* mrow = mask + (size_t)(b_ * SS + q0 + r0 + i) * SS + t0;
            Ps[r0 + i][tx]      = sa[i][0] * scale + (mrow[tx]      ? 0.f : NEGV);
            Ps[r0 + i][tx + 16] = sa[i][1] * scale + (mrow[tx + 16] ? 0.f : NEGV);
        }
        __syncthreads();

        if (tid < 64) {
            float m = rM;
            #pragma unroll
            for (int t = 0; t < 32; t++) m = fmaxf(m, Ps[tid][t]);
            const float alpha = __expf(rM - m);
            float lsum = 0.f;
            #pragma unroll
            for (int t = 0; t < 32; t++) {
                const float v = Ps[tid][t];
                const float p = __expf(v - m);
                lsum += p;
                Ps[tid][t] = (v > -5.0e9f) ? p : 0.f;
            }
            rL = rL * alpha + lsum;
            rM = m;
            rowAlpha[tid] = alpha;
        }
        __syncthreads();

        #pragma unroll
        for (int i = 0; i < 4; i++) {
            const float a = rowAlpha[r0 + i];
            #pragma unroll
            for (int j = 0; j < 4; j++) O[i][j] *= a;
        }
        #pragma unroll
        for (int t = 0; t < 32; t++) {
            const float4 vv = *(const float4*)&Vs[t][e0];
            #pragma unroll
            for (int i = 0; i < 4; i++) {
                const float p = Ps[r0 + i][t];
                O[i][0] += p * vv.x;
                O[i][1] += p * vv.y;
                O[i][2] += p * vv.z;
                O[i][3] += p * vv.w;
            }
        }
        __syncthreads();
    }

    if (tid < 64) rowInv[tid] = 1.f / rL;
    __syncthreads();

    #pragma unroll
    for (int i = 0; i < 4; i++) {
        const float inv = rowInv[r0 + i];
        float4 o;
        o.x = O[i][0] * inv; o.y = O[i][1] * inv;
        o.z = O[i][2] * inv; o.w = O[i][3] * inv;
        *(float4*)(g_attn + (size_t)(b_ * SS + q0 + r0 + i) * DD + h_ * HDIM + e0) = o;
    }
}

// ---------------------------------------------------------------------------
extern "C" void kernel_launch(void* const* d_in, const int* in_sizes, int n_in,
                              void* d_out, int out_size)
{
    const float* q    = (const float*)d_in[0];
    const float* k    = (const float*)d_in[1];
    const float* v    = (const float*)d_in[2];
    const int*   mask = (const int*)  d_in[3];
    const float* Wq   = (const float*)d_in[4];
    const float* bq   = (const float*)d_in[5];
    const float* Wk   = (const float*)d_in[6];
    const float* bk   = (const float*)d_in[7];
    const float* Wv   = (const float*)d_in[8];
    const float* bv   = (const float*)d_in[9];
    const float* Wo   = (const float*)d_in[10];
    const float* bo   = (const float*)d_in[11];
    float* out = (float*)d_out;

    dim3 g1(8, 32, 3);                 // N/128, M/128, {Q,K,V}
    proj_kernel<<<g1, 256>>>(q, k, v, Wq, Wk, Wv, bq, bk, bv);

    dim3 g2(16, 64);                   // S/64 query tiles, B*H
    attn_kernel<<<g2, 256>>>(mask);

    dim3 g3(8, 32);                    // N/128, M/128
    outproj_kernel<<<g3, 256>>>(Wo, bo, out);
}

// round 7
// speedup vs baseline: 2.7719x; 1.6514x over previous
#include <cuda_runtime.h>
#include <math.h>
#include <stdint.h>

#define BB 4
#define SS 1024
#define DD 1024
#define HH 16
#define HDIM 64
#define NEGV -10000000000.0f

// Scratch (module-load allocated; no runtime allocs)
__device__ float g_Q[BB*HH*SS*HDIM];
__device__ float g_K[BB*HH*SS*HDIM];
__device__ float g_V[BB*HH*SS*HDIM];
__device__ float g_attn[BB*SS*DD];
__device__ uint32_t g_mbits[BB*SS*(SS/32)];   // packed mask bits

// ---------------------------------------------------------------------------
// tf32 helpers
// ---------------------------------------------------------------------------
__device__ __forceinline__ uint32_t f2tf(float f) {
    uint32_t u;
    asm("cvt.rna.tf32.f32 %0, %1;" : "=r"(u) : "f"(f));
    return u;
}

__device__ __forceinline__ void mma8(float* c, const uint32_t* a, const uint32_t* b) {
    asm volatile(
        "mma.sync.aligned.m16n8k8.row.col.f32.tf32.tf32.f32 "
        "{%0,%1,%2,%3}, {%4,%5,%6,%7}, {%8,%9}, {%0,%1,%2,%3};"
        : "+f"(c[0]), "+f"(c[1]), "+f"(c[2]), "+f"(c[3])
        : "r"(a[0]), "r"(a[1]), "r"(a[2]), "r"(a[3]), "r"(b[0]), "r"(b[1]));
}

// ---------------------------------------------------------------------------
// Mask prepass: pack mask ints into bits (1 warp per 32-int word, ballot).
// ---------------------------------------------------------------------------
__global__ __launch_bounds__(256)
void maskbits_kernel(const int* __restrict__ mask)
{
    const int widx = blockIdx.x * 8 + (threadIdx.x >> 5);
    const int lanev = mask[(size_t)widx * 32 + (threadIdx.x & 31)];
    const uint32_t bal = __ballot_sync(0xffffffffu, lanev != 0);
    if ((threadIdx.x & 31) == 0) g_mbits[widx] = bal;
}

// ---------------------------------------------------------------------------
// tf32 GEMM (unchanged from R4): 128x128x16, double-buffered, 8 warps 64x32.
// ---------------------------------------------------------------------------
#define ASTR 24
#define BSTR 136

template<int MODE>
__device__ __forceinline__ void gemm_tf32(const float* __restrict__ X,
                                          const float* __restrict__ W,
                                          const float* __restrict__ bias,
                                          float* __restrict__ out)
{
    __shared__ uint32_t As[2][128][ASTR];
    __shared__ uint32_t Bs[2][16][BSTR];

    const int tid  = threadIdx.x;
    const int lane = tid & 31;
    const int w    = tid >> 5;
    const int g    = lane >> 2;
    const int q    = lane & 3;
    const int wm   = (w >> 2) * 64;
    const int wn   = (w & 3) * 32;
    const int m0   = blockIdx.y * 128;
    const int n0   = blockIdx.x * 128;

    const int aRow = tid >> 2;
    const int aC4  = (tid & 3) * 4;
    const int aBase = ((aC4 >> 3) * 8) + ((aC4 >> 2) & 1);
    const int bKK = tid >> 5;
    const int bNC = (tid & 31) * 4;

    float acc[4][4][4];
    #pragma unroll
    for (int i = 0; i < 4; i++)
        #pragma unroll
        for (int j = 0; j < 4; j++)
            #pragma unroll
            for (int r = 0; r < 4; r++) acc[i][j][r] = 0.f;

    float4 aR[2], bR[2];

    auto load_tile = [&](int kt) {
        #pragma unroll
        for (int i = 0; i < 2; i++)
            aR[i] = *(const float4*)(X + (size_t)(m0 + aRow + i * 64) * DD + kt * 16 + aC4);
        #pragma unroll
        for (int i = 0; i < 2; i++) {
            const int kk = bKK + i * 8;
            const float* p;
            if (MODE == 0) {
                const int n = n0 + bNC;
                p = W + (size_t)(n >> 6) * (DD * HDIM) + (size_t)(kt * 16 + kk) * HDIM + (n & 63);
            } else {
                p = W + (size_t)(kt * 16 + kk) * DD + n0 + bNC;
            }
            bR[i] = *(const float4*)p;
        }
    };

    auto store_tile = [&](int buf) {
        #pragma unroll
        for (int i = 0; i < 2; i++) {
            uint32_t* r = &As[buf][aRow + i * 64][0];
            r[aBase + 0] = f2tf(aR[i].x);
            r[aBase + 2] = f2tf(aR[i].y);
            r[aBase + 4] = f2tf(aR[i].z);
            r[aBase + 6] = f2tf(aR[i].w);
        }
        #pragma unroll
        for (int i = 0; i < 2; i++) {
            uint4 v;
            v.x = f2tf(bR[i].x); v.y = f2tf(bR[i].y);
            v.z = f2tf(bR[i].z); v.w = f2tf(bR[i].w);
            *(uint4*)&Bs[buf][bKK + i * 8][bNC] = v;
        }
    };

    auto compute = [&](int buf) {
        #pragma unroll
        for (int ks = 0; ks < 2; ks++) {
            uint32_t af[4][4], bf[4][2];
            #pragma unroll
            for (int mf = 0; mf < 4; mf++) {
                const int m = wm + mf * 16 + g;
                const uint2 t0 = *(const uint2*)&As[buf][m][ks * 8 + 2 * q];
                const uint2 t1 = *(const uint2*)&As[buf][m + 8][ks * 8 + 2 * q];
                af[mf][0] = t0.x; af[mf][2] = t0.y;
                af[mf][1] = t1.x; af[mf][3] = t1.y;
            }
            #pragma unroll
            for (int nf = 0; nf < 4; nf++) {
                const int n = wn + nf * 8 + g;
                bf[nf][0] = Bs[buf][ks * 8 + q][n];
                bf[nf][1] = Bs[buf][ks * 8 + q + 4][n];
            }
            #pragma unroll
            for (int mf = 0; mf < 4; mf++)
                #pragma unroll
                for (int nf = 0; nf < 4; nf++)
                    mma8(acc[mf][nf], af[mf], bf[nf]);
        }
    };

    load_tile(0);
    store_tile(0);
    __syncthreads();

    int buf = 0;
    for (int kt = 0; kt < 64; kt++) {
        if (kt < 63) load_tile(kt + 1);
        compute(buf);
        if (kt < 63) store_tile(buf ^ 1);
        __syncthreads();
        buf ^= 1;
    }

    #pragma unroll
    for (int mf = 0; mf < 4; mf++) {
        const int m = m0 + wm + mf * 16 + g;
        #pragma unroll
        for (int nf = 0; nf < 4; nf++) {
            const int n = n0 + wn + nf * 8 + 2 * q;
            const float b0v = bias[n], b1v = bias[n + 1];
            float2 v0 = make_float2(acc[mf][nf][0] + b0v, acc[mf][nf][1] + b1v);
            float2 v1 = make_float2(acc[mf][nf][2] + b0v, acc[mf][nf][3] + b1v);
            if (MODE == 0) {
                const int b_ = m >> 10, s_ = m & (SS - 1);
                const int h_ = n >> 6, e_ = n & 63;
                float* base = out + ((size_t)(b_ * HH + h_) * SS + s_) * HDIM + e_;
                *(float2*)base = v0;
                *(float2*)(base + 8 * HDIM) = v1;
            } else {
                *(float2*)(out + (size_t)m * DD + n) = v0;
                *(float2*)(out + (size_t)(m + 8) * DD + n) = v1;
            }
        }
    }
}

__global__ __launch_bounds__(256, 2)
void proj_kernel(const float* __restrict__ Xq, const float* __restrict__ Xk,
                 const float* __restrict__ Xv,
                 const float* __restrict__ Wq, const float* __restrict__ Wk,
                 const float* __restrict__ Wv,
                 const float* __restrict__ bq, const float* __restrict__ bk,
                 const float* __restrict__ bv)
{
    const float *X, *W, *bias;
    float* out;
    if (blockIdx.z == 0)      { X = Xq; W = Wq; bias = bq; out = g_Q; }
    else if (blockIdx.z == 1) { X = Xk; W = Wk; bias = bk; out = g_K; }
    else                      { X = Xv; W = Wv; bias = bv; out = g_V; }
    gemm_tf32<0>(X, W, bias, out);
}

__global__ __launch_bounds__(256, 2)
void outproj_kernel(const float* __restrict__ Wo, const float* __restrict__ bo,
                    float* __restrict__ out)
{
    gemm_tf32<1>(g_attn, Wo, bo, out);
}

// ---------------------------------------------------------------------------
// tf32 mma flash attention.
// CTA: 128 q rows of one (b,h); 8 warps; warp w owns rows 16w..16w+15.
// KV tiles of 64. Softmax row stats intra-warp (quad shfl).
// Smem (dynamic, 73728 B):
//   Ps [128][72] (permuted k-pairs) — Q staging, then P tiles (warp-private rows)
//   Ks [64][72]  (permuted dim cols) — B frags are one LDS.64, conflict-free
//   Vs [64][72]  (native [key][dim]) — B frags are LDS.32 banks 8q+g, conflict-free
// Masking identical to reference: masked logits += NEG (kept in denominator),
// numerator zeroed by mask bit.
// ---------------------------------------------------------------------------
__global__ __launch_bounds__(256, 2)
void attn_kernel()
{
    extern __shared__ uint32_t sm[];
    uint32_t* Ps = sm;              // 128*72 = 9216
    uint32_t* Ks = sm + 9216;       // 64*72  = 4608
    uint32_t* Vs = sm + 13824;      // 64*72  = 4608   (total 18432 u32 = 72 KB)

    const int bh = blockIdx.y;
    const int b_ = bh >> 4, h_ = bh & 15;
    const int q0 = blockIdx.x * 128;

    const float* Qp = g_Q + (size_t)bh * SS * HDIM;
    const float* Kp = g_K + (size_t)bh * SS * HDIM;
    const float* Vp = g_V + (size_t)bh * SS * HDIM;

    const int tid = threadIdx.x, lane = tid & 31, w = tid >> 5;
    const int g = lane >> 2, q = lane & 3;
    const int row0 = 16 * w + g;           // this thread's first q-row (local)
    const float scale = 0.03125f;          // 1/sqrt(1024)

    // permuted slots for score cols 2q, 2q+1 within an 8-col group
    const int c0col = 2 * q, c1col = 2 * q + 1;
    const int pcA = ((c0col & 3) << 1) | ((c0col >> 2) & 1);
    const int pcB = ((c1col & 3) << 1) | ((c1col >> 2) & 1);

    // ---- stage Q into Ps (tf32, k-permuted): 128x64 = 2048 float4 ----
    #pragma unroll
    for (int i = 0; i < 8; i++) {
        const int idx = tid + 256 * i;
        const int r = idx >> 4, c4 = (idx & 15) * 4;
        float4 v = *(const float4*)(Qp + (size_t)(q0 + r) * HDIM + c4);
        uint32_t* p = &Ps[r * 72 + (c4 >> 3) * 8 + ((c4 >> 2) & 1)];
        p[0] = f2tf(v.x); p[2] = f2tf(v.y); p[4] = f2tf(v.z); p[6] = f2tf(v.w);
    }
    __syncthreads();

    // ---- hoist Q fragments into registers (rows are warp-private after this) ----
    uint32_t qf[8][4];
    #pragma unroll
    for (int kk = 0; kk < 8; kk++) {
        const uint2 t0 = *(const uint2*)&Ps[row0 * 72 + kk * 8 + 2 * q];
        const uint2 t1 = *(const uint2*)&Ps[(row0 + 8) * 72 + kk * 8 + 2 * q];
        qf[kk][0] = t0.x; qf[kk][2] = t0.y;
        qf[kk][1] = t1.x; qf[kk][3] = t1.y;
    }

    float O[8][4];
    #pragma unroll
    for (int nf = 0; nf < 8; nf++)
        #pragma unroll
        for (int r = 0; r < 4; r++) O[nf][r] = 0.f;

    float mg = -1e30f, m8 = -1e30f, lg = 0.f, l8 = 0.f;

    const uint32_t* mrow  = g_mbits + ((size_t)b_ * SS + q0 + row0) * 32;
    const uint32_t* mrow8 = mrow + 8 * 32;

    for (int t0 = 0; t0 < SS; t0 += 64) {
        __syncthreads();   // prior tile's Ks/Vs reads complete

        // ---- stage K (permuted) and V (native) tiles, tf32 ----
        #pragma unroll
        for (int i = 0; i < 4; i++) {
            const int idx = tid + 256 * i;
            const int key = idx >> 4, c4 = (idx & 15) * 4;
            float4 kv = *(const float4*)(Kp + (size_t)(t0 + key) * HDIM + c4);
            uint32_t* p = &Ks[key * 72 + (c4 >> 3) * 8 + ((c4 >> 2) & 1)];
            p[0] = f2tf(kv.x); p[2] = f2tf(kv.y); p[4] = f2tf(kv.z); p[6] = f2tf(kv.w);
            float4 vv = *(const float4*)(Vp + (size_t)(t0 + key) * HDIM + c4);
            uint4 u;
            u.x = f2tf(vv.x); u.y = f2tf(vv.y); u.z = f2tf(vv.z); u.w = f2tf(vv.w);
            *(uint4*)&Vs[key * 72 + c4] = u;
        }
        __syncthreads();

        // ---- mask words for this tile (64 cols -> 2 words per row) ----
        const int wc = t0 >> 5;
        const uint64_t M0 = (uint64_t)mrow[wc]  | ((uint64_t)mrow[wc + 1]  << 32);
        const uint64_t M8 = (uint64_t)mrow8[wc] | ((uint64_t)mrow8[wc + 1] << 32);

        // ---- QK^T ----
        float s[8][4];
        #pragma unroll
        for (int nf = 0; nf < 8; nf++)
            #pragma unroll
            for (int r = 0; r < 4; r++) s[nf][r] = 0.f;

        #pragma unroll
        for (int kk = 0; kk < 8; kk++) {
            #pragma unroll
            for (int nf = 0; nf < 8; nf++) {
                const uint2 b = *(const uint2*)&Ks[(nf * 8 + g) * 72 + kk * 8 + 2 * q];
                uint32_t bf[2] = { b.x, b.y };
                mma8(s[nf], qf[kk], bf);
            }
        }

        // ---- scale + mask bias, row max ----
        float rg = -1e30f, r8 = -1e30f;
        #pragma unroll
        for (int nf = 0; nf < 8; nf++) {
            const int cA = nf * 8 + c0col, cB = nf * 8 + c1col;
            s[nf][0] = s[nf][0] * scale + (((M0 >> cA) & 1) ? 0.f : NEGV);
            s[nf][1] = s[nf][1] * scale + (((M0 >> cB) & 1) ? 0.f : NEGV);
            s[nf][2] = s[nf][2] * scale + (((M8 >> cA) & 1) ? 0.f : NEGV);
            s[nf][3] = s[nf][3] * scale + (((M8 >> cB) & 1) ? 0.f : NEGV);
            rg = fmaxf(rg, fmaxf(s[nf][0], s[nf][1]));
            r8 = fmaxf(r8, fmaxf(s[nf][2], s[nf][3]));
        }
        rg = fmaxf(rg, __shfl_xor_sync(0xffffffffu, rg, 1));
        rg = fmaxf(rg, __shfl_xor_sync(0xffffffffu, rg, 2));
        r8 = fmaxf(r8, __shfl_xor_sync(0xffffffffu, r8, 1));
        r8 = fmaxf(r8, __shfl_xor_sync(0xffffffffu, r8, 2));

        const float mngv = fmaxf(mg, rg), mn8v = fmaxf(m8, r8);
        const float ag = __expf(mg - mngv), a8 = __expf(m8 - mn8v);
        mg = mngv; m8 = mn8v;

        // ---- exp, denominator, store P (numerator masked) ----
        uint32_t* prow  = &Ps[row0 * 72];
        uint32_t* prow8 = &Ps[(row0 + 8) * 72];
        float sg = 0.f, s8sum = 0.f;
        #pragma unroll
        for (int nf = 0; nf < 8; nf++) {
            const int cA = nf * 8 + c0col, cB = nf * 8 + c1col;
            const float p0 = __expf(s[nf][0] - mg);
            const float p1 = __expf(s[nf][1] - mg);
            const float p2 = __expf(s[nf][2] - m8);
            const float p3 = __expf(s[nf][3] - m8);
            sg += p0 + p1; s8sum += p2 + p3;
            prow[nf * 8 + pcA]  = f2tf(((M0 >> cA) & 1) ? p0 : 0.f);
            prow[nf * 8 + pcB]  = f2tf(((M0 >> cB) & 1) ? p1 : 0.f);
            prow8[nf * 8 + pcA] = f2tf(((M8 >> cA) & 1) ? p2 : 0.f);
            prow8[nf * 8 + pcB] = f2tf(((M8 >> cB) & 1) ? p3 : 0.f);
            O[nf][0] *= ag; O[nf][1] *= ag;
            O[nf][2] *= a8; O[nf][3] *= a8;
        }
        sg    += __shfl_xor_sync(0xffffffffu, sg, 1);
        sg    += __shfl_xor_sync(0xffffffffu, sg, 2);
        s8sum += __shfl_xor_sync(0xffffffffu, s8sum, 1);
        s8sum += __shfl_xor_sync(0xffffffffu, s8sum, 2);
        lg = lg * ag + sg;
        l8 = l8 * a8 + s8sum;

        __syncwarp();

        // ---- P @ V ----
        #pragma unroll
        for (int kk = 0; kk < 8; kk++) {
            const uint2 t0v = *(const uint2*)&Ps[row0 * 72 + kk * 8 + 2 * q];
            const uint2 t1v = *(const uint2*)&Ps[(row0 + 8) * 72 + kk * 8 + 2 * q];
            uint32_t af[4] = { t0v.x, t1v.x, t0v.y, t1v.y };
            #pragma unroll
            for (int nf = 0; nf < 8; nf++) {
                uint32_t bf[2] = { Vs[(kk * 8 + q) * 72 + nf * 8 + g],
                                   Vs[(kk * 8 + q + 4) * 72 + nf * 8 + g] };
                mma8(O[nf], af, bf);
            }
        }
    }

    // ---- epilogue ----
    const float ig = 1.f / lg, i8 = 1.f / l8;
    float* orow  = g_attn + (size_t)(b_ * SS + q0 + row0) * DD + h_ * HDIM;
    float* orow8 = orow + 8 * DD;
    #pragma unroll
    for (int nf = 0; nf < 8; nf++) {
        const int e = nf * 8 + 2 * q;
        *(float2*)(orow  + e) = make_float2(O[nf][0] * ig, O[nf][1] * ig);
        *(float2*)(orow8 + e) = make_float2(O[nf][2] * i8, O[nf][3] * i8);
    }
}

// ---------------------------------------------------------------------------
extern "C" void kernel_launch(void* const* d_in, const int* in_sizes, int n_in,
                              void* d_out, int out_size)
{
    const float* q    = (const float*)d_in[0];
    const float* k    = (const float*)d_in[1];
    const float* v    = (const float*)d_in[2];
    const int*   mask = (const int*)  d_in[3];
    const float* Wq   = (const float*)d_in[4];
    const float* bq   = (const float*)d_in[5];
    const float* Wk   = (const float*)d_in[6];
    const float* bk   = (const float*)d_in[7];
    const float* Wv   = (const float*)d_in[8];
    const float* bv   = (const float*)d_in[9];
    const float* Wo   = (const float*)d_in[10];
    const float* bo   = (const float*)d_in[11];
    float* out = (float*)d_out;

    cudaFuncSetAttribute(attn_kernel,
                         cudaFuncAttributeMaxDynamicSharedMemorySize, 73728);

    maskbits_kernel<<<BB * SS * (SS / 32) / 8, 256>>>(mask);

    dim3 g1(8, 32, 3);                 // N/128, M/128, {Q,K,V}
    proj_kernel<<<g1, 256>>>(q, k, v, Wq, Wk, Wv, bq, bk, bv);

    dim3 g2(8, 64);                    // S/128 q-tiles, B*H
    attn_kernel<<<g2, 256, 73728>>>();

    dim3 g3(8, 32);                    // N/128, M/128
    outproj_kernel<<<g3, 256>>>(Wo, bo, out);
}

// round 11
// speedup vs baseline: 4.5245x; 1.6323x over previous
#include <cuda_runtime.h>
#include <cuda_fp16.h>
#include <math.h>
#include <stdint.h>

#define BB 4
#define SS 1024
#define DD 1024
#define HH 16
#define HDIM 64
#define NEGV -10000000000.0f

// Scratch (module-load allocated; no runtime allocs)
__device__ __half g_Q[BB*HH*SS*HDIM];
__device__ __half g_K[BB*HH*SS*HDIM];
__device__ __half g_V[BB*HH*SS*HDIM];
__device__ float  g_attn[BB*SS*DD];
__device__ uint32_t g_mbits[BB*SS*(SS/32)];   // packed mask bits
__device__ float g_Wt[3*DD*DD];               // Wq/Wk/Wv transposed to [n][k]
__device__ float g_Wot[DD*DD];                // Wo transposed to [n][k]

// ---------------------------------------------------------------------------
// helpers
// ---------------------------------------------------------------------------
__device__ __forceinline__ uint32_t f2h2(float lo, float hi) {
    __half2 h = __floats2half2_rn(lo, hi);
    return *reinterpret_cast<uint32_t*>(&h);
}

__device__ __forceinline__ void mma16(float* c, const uint32_t* a, const uint32_t* b) {
    asm volatile(
        "mma.sync.aligned.m16n8k16.row.col.f32.f16.f16.f32 "
        "{%0,%1,%2,%3}, {%4,%5,%6,%7}, {%8,%9}, {%0,%1,%2,%3};"
        : "+f"(c[0]), "+f"(c[1]), "+f"(c[2]), "+f"(c[3])
        : "r"(a[0]), "r"(a[1]), "r"(a[2]), "r"(a[3]), "r"(b[0]), "r"(b[1]));
}

__device__ __forceinline__ uint32_t smem_u32(const void* p) {
    uint32_t a;
    asm("{ .reg .u64 t; cvta.to.shared.u64 t, %1; cvt.u32.u64 %0, t; }"
        : "=r"(a) : "l"(p));
    return a;
}

__device__ __forceinline__ void ldsm_x4(uint32_t* r, uint32_t a) {
    asm volatile("ldmatrix.sync.aligned.m8n8.x4.shared.b16 {%0,%1,%2,%3}, [%4];"
        : "=r"(r[0]), "=r"(r[1]), "=r"(r[2]), "=r"(r[3]) : "r"(a));
}
__device__ __forceinline__ void ldsm_x2(uint32_t* r, uint32_t a) {
    asm volatile("ldmatrix.sync.aligned.m8n8.x2.shared.b16 {%0,%1}, [%2];"
        : "=r"(r[0]), "=r"(r[1]) : "r"(a));
}
__device__ __forceinline__ void ldsm_x2t(uint32_t* r, uint32_t a) {
    asm volatile("ldmatrix.sync.aligned.m8n8.x2.trans.shared.b16 {%0,%1}, [%2];"
        : "=r"(r[0]), "=r"(r[1]) : "r"(a));
}

// ---------------------------------------------------------------------------
// Mask prepass: pack mask ints into bits (1 warp per 32-int word, ballot).
// ---------------------------------------------------------------------------
__global__ __launch_bounds__(256)
void maskbits_kernel(const int* __restrict__ mask)
{
    const int widx = blockIdx.x * 8 + (threadIdx.x >> 5);
    const int lanev = mask[(size_t)widx * 32 + (threadIdx.x & 31)];
    const uint32_t bal = __ballot_sync(0xffffffffu, lanev != 0);
    if ((threadIdx.x & 31) == 0) g_mbits[widx] = bal;
}

// ---------------------------------------------------------------------------
// Weight transpose: W -> [n][k] row-major scratch.
// z=0..2: proj W[h][k][e] -> g_Wt[z][n=h*64+e][k];  z=3: Wo[k][n] -> g_Wot[n][k]
// ---------------------------------------------------------------------------
__global__ __launch_bounds__(256)
void transpose_w(const float* __restrict__ Wq, const float* __restrict__ Wk,
                 const float* __restrict__ Wv, const float* __restrict__ Wo)
{
    __shared__ float t[32][33];
    const int z = blockIdx.z;
    const float* W = (z == 0) ? Wq : (z == 1) ? Wk : (z == 2) ? Wv : Wo;
    float* out = (z < 3) ? (g_Wt + (size_t)z * DD * DD) : g_Wot;
    const int n0 = blockIdx.x * 32, k0 = blockIdx.y * 32;
    const int tx = threadIdx.x & 31, ty = threadIdx.x >> 5;

    #pragma unroll
    for (int j = 0; j < 4; j++) {
        const int k = k0 + ty + 8 * j;
        const int n = n0 + tx;
        const float v = (z < 3)
            ? W[(size_t)(n >> 6) * (DD * HDIM) + (size_t)k * HDIM + (n & 63)]
            : W[(size_t)k * DD + n];
        t[ty + 8 * j][tx] = v;
    }
    __syncthreads();
    #pragma unroll
    for (int j = 0; j < 4; j++) {
        const int n = n0 + ty + 8 * j;
        const int k = k0 + tx;
        out[(size_t)n * DD + k] = t[tx][ty + 8 * j];
    }
}

// ---------------------------------------------------------------------------
// fp16 GEMM: C[4096,1024] = X @ Wt^T + bias (X, Wt fp32; converted to fp16).
// 128x128x32 tiles, double-buffered, 8 warps of 64x32, m16n8k16 fragments
// via ldmatrix. Smem rows stride 72 halves (144B) -> conflict-free LDSM.
// MODE 0: output -> g_{Q,K,V} fp16 scattered [B,H,S,64]
// MODE 1: output -> fp32 row-major (d_out)
// dyn smem: A0[128][72] A1 B0 B1 = 4 * 18432 B = 73728 B
// ---------------------------------------------------------------------------
template<int MODE>
__device__ __forceinline__ void gemm_f16_body(const float* __restrict__ X,
                                              const float* __restrict__ Wt,
                                              const float* __restrict__ bias,
                                              void* __restrict__ outp)
{
    extern __shared__ __half hsm[];
    const int tid = threadIdx.x, lane = tid & 31, w = tid >> 5;
    const int g = lane >> 2, q = lane & 3;
    const int l7 = lane & 7, lb3 = (lane >> 3) & 1, lb4 = lane >> 4;
    const int wm = (w >> 2) * 64, wn = (w & 3) * 32;
    const int m0 = blockIdx.y * 128, n0 = blockIdx.x * 128;
    const uint32_t sbase = smem_u32(hsm);

    float acc[4][4][4];
    #pragma unroll
    for (int i = 0; i < 4; i++)
        #pragma unroll
        for (int j = 0; j < 4; j++)
            #pragma unroll
            for (int r = 0; r < 4; r++) acc[i][j][r] = 0.f;

    uint2 aH[4], bH[4];
    const int ldR = tid >> 3, ldC = (tid & 7) * 4;   // row 0..127? no: covers below

    auto ldg = [&](int kt) {
        const int kb = kt * 32;
        #pragma unroll
        for (int i = 0; i < 4; i++) {
            const int idx = tid + 256 * i;
            const int r = idx >> 3, c4 = (idx & 7) * 4;
            float4 a = *(const float4*)(X  + (size_t)(m0 + r) * DD + kb + c4);
            float4 b = *(const float4*)(Wt + (size_t)(n0 + r) * DD + kb + c4);
            aH[i] = make_uint2(f2h2(a.x, a.y), f2h2(a.z, a.w));
            bH[i] = make_uint2(f2h2(b.x, b.y), f2h2(b.z, b.w));
        }
    };
    auto sts = [&](int buf) {
        __half* Ab = hsm + buf * 9216;
        __half* Bb = hsm + 18432 + buf * 9216;
        #pragma unroll
        for (int i = 0; i < 4; i++) {
            const int idx = tid + 256 * i;
            const int r = idx >> 3, c4 = (idx & 7) * 4;
            *(uint2*)&Ab[r * 72 + c4] = aH[i];
            *(uint2*)&Bb[r * 72 + c4] = bH[i];
        }
    };
    auto compute = [&](int buf) {
        const uint32_t Abase = sbase + buf * 18432;
        const uint32_t Bbase = sbase + 36864 + buf * 18432;
        #pragma unroll
        for (int ks = 0; ks < 2; ks++) {
            uint32_t af[4][4], bf[4][2];
            #pragma unroll
            for (int mf = 0; mf < 4; mf++) {
                const int row = wm + mf * 16 + l7 + 8 * lb3;
                ldsm_x4(af[mf], Abase + (uint32_t)(row * 144 + (ks * 16 + 8 * lb4) * 2));
            }
            #pragma unroll
            for (int nfp = 0; nfp < 2; nfp++) {
                uint32_t t4[4];
                const int row = wn + nfp * 16 + 8 * lb4 + l7;
                ldsm_x4(t4, Bbase + (uint32_t)(row * 144 + (ks * 16 + 8 * lb3) * 2));
                bf[2 * nfp][0] = t4[0]; bf[2 * nfp][1] = t4[1];
                bf[2 * nfp + 1][0] = t4[2]; bf[2 * nfp + 1][1] = t4[3];
            }
            #pragma unroll
            for (int mf = 0; mf < 4; mf++)
                #pragma unroll
                for (int nf = 0; nf < 4; nf++)
                    mma16(acc[mf][nf], af[mf], bf[nf]);
        }
    };

    ldg(0); sts(0);
    __syncthreads();

    for (int kt = 0; kt < 32; kt++) {
        const int buf = kt & 1;
        if (kt < 31) ldg(kt + 1);
        compute(buf);
        if (kt < 31) sts(buf ^ 1);
        __syncthreads();
    }

    // epilogue
    #pragma unroll
    for (int mf = 0; mf < 4; mf++) {
        const int m = m0 + wm + mf * 16 + g;
        #pragma unroll
        for (int nf = 0; nf < 4; nf++) {
            const int n = n0 + wn + nf * 8 + 2 * q;
            const float b0v = bias[n], b1v = bias[n + 1];
            const float o0 = acc[mf][nf][0] + b0v, o1 = acc[mf][nf][1] + b1v;
            const float o2 = acc[mf][nf][2] + b0v, o3 = acc[mf][nf][3] + b1v;
            if (MODE == 0) {
                __half* out = (__half*)outp;
                const int b_ = m >> 10, s_ = m & (SS - 1);
                const int h_ = n >> 6, e_ = n & 63;
                __half* base = out + ((size_t)(b_ * HH + h_) * SS + s_) * HDIM + e_;
                *(uint32_t*)base = f2h2(o0, o1);
                *(uint32_t*)(base + 8 * HDIM) = f2h2(o2, o3);
            } else {
                float* out = (float*)outp;
                *(float2*)(out + (size_t)m * DD + n) = make_float2(o0, o1);
                *(float2*)(out + (size_t)(m + 8) * DD + n) = make_float2(o2, o3);
            }
        }
    }
}

__global__ __launch_bounds__(256, 2)
void proj_kernel(const float* __restrict__ Xq, const float* __restrict__ Xk,
                 const float* __restrict__ Xv,
                 const float* __restrict__ bq, const float* __restrict__ bk,
                 const float* __restrict__ bv)
{
    const float *X, *bias, *Wt;
    __half* out;
    if (blockIdx.z == 0)      { X = Xq; Wt = g_Wt;               bias = bq; out = g_Q; }
    else if (blockIdx.z == 1) { X = Xk; Wt = g_Wt + DD * DD;     bias = bk; out = g_K; }
    else                      { X = Xv; Wt = g_Wt + 2 * DD * DD; bias = bv; out = g_V; }
    gemm_f16_body<0>(X, Wt, bias, out);
}

__global__ __launch_bounds__(256, 2)
void outproj_kernel(const float* __restrict__ bo, float* __restrict__ out)
{
    gemm_f16_body<1>(g_attn, g_Wot, bo, out);
}

// ---------------------------------------------------------------------------
// fp16 mma flash attention, register-resident P.
// CTA: 128 q rows of one (b,h); 8 warps; warp w owns rows 16w..16w+15.
// KV tiles of 64, prefetched into registers (overlap with compute).
// P never touches smem: QK C-fragment (g,2q)(g,2q+1)(g+8,..) maps exactly
// onto the PV A-fragment -> pack masked exp values with f2h2 in registers.
// Smem 18432 B: Qs[128][72] (staging only), then Ks[64][72] / Vs[64][72].
// Masking identical to reference: masked logits += NEG (kept in denominator),
// numerator zeroed by mask bit.
// ---------------------------------------------------------------------------
__global__ __launch_bounds__(256, 2)
void attn_kernel()
{
    extern __shared__ __half hsm[];
    __half* Qs = hsm;            // [128][72] during staging
    __half* Ks = hsm;            // [64][72] after Q hoist
    __half* Vs = hsm + 64 * 72;  // [64][72]

    const int bh = blockIdx.y;
    const int b_ = bh >> 4, h_ = bh & 15;
    const int q0 = blockIdx.x * 128;

    const __half* Qp = g_Q + (size_t)bh * SS * HDIM;
    const __half* Kp = g_K + (size_t)bh * SS * HDIM;
    const __half* Vp = g_V + (size_t)bh * SS * HDIM;

    const int tid = threadIdx.x, lane = tid & 31, w = tid >> 5;
    const int g = lane >> 2, q = lane & 3;
    const int l7 = lane & 7, lb3 = (lane >> 3) & 1, lb4 = lane >> 4;
    const int row0 = 16 * w + g;
    const float scale = 0.03125f;

    // ---- stage Q (fp16 copy): 128x64 halves = 1024 uint4 ----
    #pragma unroll
    for (int i = 0; i < 4; i++) {
        const int idx = tid + 256 * i;
        const int r = idx >> 3, c8 = (idx & 7) * 8;
        *(uint4*)&Qs[r * 72 + c8] = *(const uint4*)(Qp + (size_t)(q0 + r) * HDIM + c8);
    }
    __syncthreads();

    // ---- hoist Q fragments (ldmatrix x4 per 16-k block) ----
    uint32_t qf[4][4];
    {
        const uint32_t qb = smem_u32(Qs);
        const int row = 16 * w + l7 + 8 * lb3;
        #pragma unroll
        for (int ks = 0; ks < 4; ks++)
            ldsm_x4(qf[ks], qb + (uint32_t)(row * 144 + (ks * 16 + 8 * lb4) * 2));
    }

    float O[8][4];
    #pragma unroll
    for (int nf = 0; nf < 8; nf++)
        #pragma unroll
        for (int r = 0; r < 4; r++) O[nf][r] = 0.f;

    float mg = -1e30f, m8 = -1e30f, lg = 0.f, l8 = 0.f;

    const uint32_t* mrow  = g_mbits + ((size_t)b_ * SS + q0 + row0) * 32;
    const uint32_t* mrow8 = mrow + 8 * 32;

    // ---- prefetch KV tile 0 (64x64 halves = 512 uint4 each) ----
    uint4 kH[2], vH[2];
    auto ldgKV = [&](int t0) {
        #pragma unroll
        for (int i = 0; i < 2; i++) {
            const int idx = tid + 256 * i;
            const int key = idx >> 3, c8 = (idx & 7) * 8;
            kH[i] = *(const uint4*)(Kp + (size_t)(t0 + key) * HDIM + c8);
            vH[i] = *(const uint4*)(Vp + (size_t)(t0 + key) * HDIM + c8);
        }
    };
    ldgKV(0);
    __syncthreads();   // all Q hoists done before Ks/Vs overwrite Qs

    const uint32_t kb = smem_u32(Ks), vb = smem_u32(Vs);

    for (int t0 = 0; t0 < SS; t0 += 64) {
        // ---- store KV tile ----
        #pragma unroll
        for (int i = 0; i < 2; i++) {
            const int idx = tid + 256 * i;
            const int key = idx >> 3, c8 = (idx & 7) * 8;
            *(uint4*)&Ks[key * 72 + c8] = kH[i];
            *(uint4*)&Vs[key * 72 + c8] = vH[i];
        }
        __syncthreads();
        if (t0 + 64 < SS) ldgKV(t0 + 64);   // overlaps compute below

        const int wc = t0 >> 5;
        const uint64_t M0 = (uint64_t)mrow[wc]  | ((uint64_t)mrow[wc + 1]  << 32);
        const uint64_t M8 = (uint64_t)mrow8[wc] | ((uint64_t)mrow8[wc + 1] << 32);

        // ---- QK^T ----
        float s[8][4];
        #pragma unroll
        for (int nf = 0; nf < 8; nf++)
            #pragma unroll
            for (int r = 0; r < 4; r++) s[nf][r] = 0.f;

        #pragma unroll
        for (int ks = 0; ks < 4; ks++) {
            #pragma unroll
            for (int nf = 0; nf < 8; nf++) {
                uint32_t bf[2];
                ldsm_x2(bf, kb + (uint32_t)((nf * 8 + l7) * 144 + (ks * 16 + 8 * lb3) * 2));
                mma16(s[nf], qf[ks], bf);
            }
        }

        // ---- scale + mask bias, row max ----
        float rg = -1e30f, r8 = -1e30f;
        #pragma unroll
        for (int nf = 0; nf < 8; nf++) {
            const int cA = nf * 8 + 2 * q, cB = cA + 1;
            s[nf][0] = s[nf][0] * scale + (((M0 >> cA) & 1) ? 0.f : NEGV);
            s[nf][1] = s[nf][1] * scale + (((M0 >> cB) & 1) ? 0.f : NEGV);
            s[nf][2] = s[nf][2] * scale + (((M8 >> cA) & 1) ? 0.f : NEGV);
            s[nf][3] = s[nf][3] * scale + (((M8 >> cB) & 1) ? 0.f : NEGV);
            rg = fmaxf(rg, fmaxf(s[nf][0], s[nf][1]));
            r8 = fmaxf(r8, fmaxf(s[nf][2], s[nf][3]));
        }
        rg = fmaxf(rg, __shfl_xor_sync(0xffffffffu, rg, 1));
        rg = fmaxf(rg, __shfl_xor_sync(0xffffffffu, rg, 2));
        r8 = fmaxf(r8, __shfl_xor_sync(0xffffffffu, r8, 1));
        r8 = fmaxf(r8, __shfl_xor_sync(0xffffffffu, r8, 2));

        const float mng = fmaxf(mg, rg), mn8 = fmaxf(m8, r8);
        const float ag = __expf(mg - mng), a8 = __expf(m8 - mn8);
        mg = mng; m8 = mn8;

        // ---- exp; denominator counts masked terms, numerator masked ----
        float sg = 0.f, s8sum = 0.f;
        #pragma unroll
        for (int nf = 0; nf < 8; nf++) {
            const int cA = nf * 8 + 2 * q, cB = cA + 1;
            const float p0 = __expf(s[nf][0] - mg);
            const float p1 = __expf(s[nf][1] - mg);
            const float p2 = __expf(s[nf][2] - m8);
            const float p3 = __expf(s[nf][3] - m8);
            sg += p0 + p1; s8sum += p2 + p3;
            s[nf][0] = ((M0 >> cA) & 1) ? p0 : 0.f;
            s[nf][1] = ((M0 >> cB) & 1) ? p1 : 0.f;
            s[nf][2] = ((M8 >> cA) & 1) ? p2 : 0.f;
            s[nf][3] = ((M8 >> cB) & 1) ? p3 : 0.f;
            O[nf][0] *= ag; O[nf][1] *= ag;
            O[nf][2] *= a8; O[nf][3] *= a8;
        }
        sg    += __shfl_xor_sync(0xffffffffu, sg, 1);
        sg    += __shfl_xor_sync(0xffffffffu, sg, 2);
        s8sum += __shfl_xor_sync(0xffffffffu, s8sum, 1);
        s8sum += __shfl_xor_sync(0xffffffffu, s8sum, 2);
        lg = lg * ag + sg;
        l8 = l8 * a8 + s8sum;

        // ---- P @ V : P packed from registers (QK C-frag == PV A-frag) ----
        #pragma unroll
        for (int ks = 0; ks < 4; ks++) {
            uint32_t pf[4];
            pf[0] = f2h2(s[2 * ks][0],     s[2 * ks][1]);
            pf[1] = f2h2(s[2 * ks][2],     s[2 * ks][3]);
            pf[2] = f2h2(s[2 * ks + 1][0], s[2 * ks + 1][1]);
            pf[3] = f2h2(s[2 * ks + 1][2], s[2 * ks + 1][3]);
            #pragma unroll
            for (int nf = 0; nf < 8; nf++) {
                uint32_t bf[2];
                ldsm_x2t(bf, vb + (uint32_t)((ks * 16 + (lane & 15)) * 144 + nf * 16));
                mma16(O[nf], pf, bf);
            }
        }
        __syncthreads();   // Ks/Vs reads done before next tile's stores
    }

    // ---- epilogue ----
    const float ig = 1.f / lg, i8 = 1.f / l8;
    float* orow  = g_attn + (size_t)(b_ * SS + q0 + row0) * DD + h_ * HDIM;
    float* orow8 = orow + 8 * DD;
    #pragma unroll
    for (int nf = 0; nf < 8; nf++) {
        const int e = nf * 8 + 2 * q;
        *(float2*)(orow  + e) = make_float2(O[nf][0] * ig, O[nf][1] * ig);
        *(float2*)(orow8 + e) = make_float2(O[nf][2] * i8, O[nf][3] * i8);
    }
}

// ---------------------------------------------------------------------------
extern "C" void kernel_launch(void* const* d_in, const int* in_sizes, int n_in,
                              void* d_out, int out_size)
{
    const float* q    = (const float*)d_in[0];
    const float* k    = (const float*)d_in[1];
    const float* v    = (const float*)d_in[2];
    const int*   mask = (const int*)  d_in[3];
    const float* Wq   = (const float*)d_in[4];
    const float* bq   = (const float*)d_in[5];
    const float* Wk   = (const float*)d_in[6];
    const float* bk   = (const float*)d_in[7];
    const float* Wv   = (const float*)d_in[8];
    const float* bv   = (const float*)d_in[9];
    const float* Wo   = (const float*)d_in[10];
    const float* bo   = (const float*)d_in[11];
    float* out = (float*)d_out;

    cudaFuncSetAttribute(proj_kernel,
                         cudaFuncAttributeMaxDynamicSharedMemorySize, 73728);
    cudaFuncSetAttribute(outproj_kernel,
                         cudaFuncAttributeMaxDynamicSharedMemorySize, 73728);

    maskbits_kernel<<<BB * SS * (SS / 32) / 8, 256>>>(mask);

    transpose_w<<<dim3(32, 32, 4), 256>>>(Wq, Wk, Wv, Wo);

    dim3 g1(8, 32, 3);                 // N/128, M/128, {Q,K,V}
    proj_kernel<<<g1, 256, 73728>>>(q, k, v, bq, bk, bv);

    dim3 g2(8, 64);                    // S/128 q-tiles, B*H
    attn_kernel<<<g2, 256, 18432>>>();

    dim3 g3(8, 32);                    // N/128, M/128
    outproj_kernel<<<g3, 256, 73728>>>(bo, out);
}

// round 12
// speedup vs baseline: 5.6713x; 1.2535x over previous
#include <cuda_runtime.h>
#include <cuda_fp16.h>
#include <math.h>
#include <stdint.h>

#define BB 4
#define SS 1024
#define DD 1024
#define HH 16
#define HDIM 64
#define NEGV -10000000000.0f

// Scratch (module-load allocated; no runtime allocs)
__device__ __half g_Xh[3*BB*SS*DD];           // Xq/Xk/Xv pre-converted to fp16
__device__ __half g_Q[BB*HH*SS*HDIM];
__device__ __half g_K[BB*HH*SS*HDIM];
__device__ __half g_V[BB*HH*SS*HDIM];
__device__ __half g_attn[BB*SS*DD];
__device__ uint32_t g_mbits[BB*SS*(SS/32)];   // packed mask bits
__device__ __half g_Wt[3*DD*DD];              // Wq/Wk/Wv transposed to [n][k], fp16
__device__ __half g_Wot[DD*DD];               // Wo transposed to [n][k], fp16

// ---------------------------------------------------------------------------
// helpers
// ---------------------------------------------------------------------------
__device__ __forceinline__ uint32_t f2h2(float lo, float hi) {
    __half2 h = __floats2half2_rn(lo, hi);
    return *reinterpret_cast<uint32_t*>(&h);
}

__device__ __forceinline__ void mma16(float* c, const uint32_t* a, const uint32_t* b) {
    asm volatile(
        "mma.sync.aligned.m16n8k16.row.col.f32.f16.f16.f32 "
        "{%0,%1,%2,%3}, {%4,%5,%6,%7}, {%8,%9}, {%0,%1,%2,%3};"
        : "+f"(c[0]), "+f"(c[1]), "+f"(c[2]), "+f"(c[3])
        : "r"(a[0]), "r"(a[1]), "r"(a[2]), "r"(a[3]), "r"(b[0]), "r"(b[1]));
}

__device__ __forceinline__ uint32_t smem_u32(const void* p) {
    uint32_t a;
    asm("{ .reg .u64 t; cvta.to.shared.u64 t, %1; cvt.u32.u64 %0, t; }"
        : "=r"(a) : "l"(p));
    return a;
}

__device__ __forceinline__ void ldsm_x4(uint32_t* r, uint32_t a) {
    asm volatile("ldmatrix.sync.aligned.m8n8.x4.shared.b16 {%0,%1,%2,%3}, [%4];"
        : "=r"(r[0]), "=r"(r[1]), "=r"(r[2]), "=r"(r[3]) : "r"(a));
}
__device__ __forceinline__ void ldsm_x4t(uint32_t* r, uint32_t a) {
    asm volatile("ldmatrix.sync.aligned.m8n8.x4.trans.shared.b16 {%0,%1,%2,%3}, [%4];"
        : "=r"(r[0]), "=r"(r[1]), "=r"(r[2]), "=r"(r[3]) : "r"(a));
}

__device__ __forceinline__ void cpa16(uint32_t dst, const void* src) {
    asm volatile("cp.async.cg.shared.global [%0], [%1], 16;" :: "r"(dst), "l"(src));
}
#define CPA_COMMIT() asm volatile("cp.async.commit_group;")
#define CPA_WAIT0()  asm volatile("cp.async.wait_group 0;")
#define CPA_WAIT1()  asm volatile("cp.async.wait_group 1;")

// ---------------------------------------------------------------------------
// Prepass kernels
// ---------------------------------------------------------------------------
__global__ __launch_bounds__(256)
void maskbits_kernel(const int* __restrict__ mask)
{
    const int widx = blockIdx.x * 8 + (threadIdx.x >> 5);
    const int lanev = mask[(size_t)widx * 32 + (threadIdx.x & 31)];
    const uint32_t bal = __ballot_sync(0xffffffffu, lanev != 0);
    if ((threadIdx.x & 31) == 0) g_mbits[widx] = bal;
}

// fp32 -> fp16 conversion of the three X inputs (numerics identical to
// converting inside the GEMM ldg, which is what R10 did).
__global__ __launch_bounds__(256)
void x2h_kernel(const float* __restrict__ Xq, const float* __restrict__ Xk,
                const float* __restrict__ Xv)
{
    const int z = blockIdx.z;
    const float* src = (z == 0) ? Xq : (z == 1) ? Xk : Xv;
    __half* dst = g_Xh + (size_t)z * (BB * SS * DD);
    const size_t i8 = ((size_t)blockIdx.x * 256 + threadIdx.x) * 8;
    float4 a = *(const float4*)(src + i8);
    float4 b = *(const float4*)(src + i8 + 4);
    uint4 o;
    o.x = f2h2(a.x, a.y); o.y = f2h2(a.z, a.w);
    o.z = f2h2(b.x, b.y); o.w = f2h2(b.z, b.w);
    *(uint4*)(dst + i8) = o;
}

// Weight transpose -> [n][k] fp16 scratch.
// z=0..2: proj W[h][k][e] -> g_Wt[z][n=h*64+e][k];  z=3: Wo[k][n] -> g_Wot[n][k]
__global__ __launch_bounds__(256)
void transpose_w(const float* __restrict__ Wq, const float* __restrict__ Wk,
                 const float* __restrict__ Wv, const float* __restrict__ Wo)
{
    __shared__ float t[32][33];
    const int z = blockIdx.z;
    const float* W = (z == 0) ? Wq : (z == 1) ? Wk : (z == 2) ? Wv : Wo;
    __half* out = (z < 3) ? (g_Wt + (size_t)z * DD * DD) : g_Wot;
    const int n0 = blockIdx.x * 32, k0 = blockIdx.y * 32;
    const int tx = threadIdx.x & 31, ty = threadIdx.x >> 5;

    #pragma unroll
    for (int j = 0; j < 4; j++) {
        const int k = k0 + ty + 8 * j;
        const int n = n0 + tx;
        const float v = (z < 3)
            ? W[(size_t)(n >> 6) * (DD * HDIM) + (size_t)k * HDIM + (n & 63)]
            : W[(size_t)k * DD + n];
        t[ty + 8 * j][tx] = v;
    }
    __syncthreads();
    #pragma unroll
    for (int j = 0; j < 4; j++) {
        const int n = n0 + ty + 8 * j;
        const int k = k0 + tx;
        out[(size_t)n * DD + k] = __float2half_rn(t[tx][ty + 8 * j]);
    }
}

// ---------------------------------------------------------------------------
// fp16 GEMM: C[4096,1024] = X @ Wt^T + bias, X and Wt already fp16.
// 128x128x32 tiles, cp.async double-buffered (A and B), 8 warps of 64x32,
// m16n8k16 via ldmatrix. Smem rows stride 72 halves (144B) -> conflict-free.
// MODE 0: output -> g_{Q,K,V} fp16 scattered [B,H,S,64]
// MODE 1: output -> fp32 row-major (d_out)
// dyn smem: 2 bufs x (A[128][72] + B[128][72]) = 2*36864 = 73728 B
// ---------------------------------------------------------------------------
template<int MODE>
__device__ __forceinline__ void gemm_f16_body(const __half* __restrict__ X,
                                              const __half* __restrict__ Wt,
                                              const float* __restrict__ bias,
                                              void* __restrict__ outp)
{
    extern __shared__ __half hsm[];
    const int tid = threadIdx.x, lane = tid & 31, w = tid >> 5;
    const int g = lane >> 2, q = lane & 3;
    const int l7 = lane & 7, lb3 = (lane >> 3) & 1, lb4 = lane >> 4;
    const int wm = (w >> 2) * 64, wn = (w & 3) * 32;
    const int m0 = blockIdx.y * 128, n0 = blockIdx.x * 128;
    const uint32_t sbase = smem_u32(hsm);

    float acc[4][4][4];
    #pragma unroll
    for (int i = 0; i < 4; i++)
        #pragma unroll
        for (int j = 0; j < 4; j++)
            #pragma unroll
            for (int r = 0; r < 4; r++) acc[i][j][r] = 0.f;

    // per-thread tile-load mapping: 512 chunks of 8 halves per operand
    const int ldRow = tid >> 2, ldC8 = (tid & 3) * 8;

    auto ldg_async = [&](int kt, int buf) {
        const int kb = kt * 32;
        const uint32_t abase = sbase + buf * 36864;
        #pragma unroll
        for (int i = 0; i < 2; i++) {
            const int row = ldRow + i * 64;
            const uint32_t off = (uint32_t)(row * 144 + ldC8 * 2);
            cpa16(abase + off,         X  + (size_t)(m0 + row) * DD + kb + ldC8);
            cpa16(abase + 18432 + off, Wt + (size_t)(n0 + row) * DD + kb + ldC8);
        }
    };

    auto compute = [&](int buf) {
        const uint32_t Abase = sbase + buf * 36864;
        const uint32_t Bbase = Abase + 18432;
        #pragma unroll
        for (int ks = 0; ks < 2; ks++) {
            uint32_t af[4][4], bf[4][2];
            #pragma unroll
            for (int mf = 0; mf < 4; mf++) {
                const int row = wm + mf * 16 + l7 + 8 * lb3;
                ldsm_x4(af[mf], Abase + (uint32_t)(row * 144 + (ks * 16 + 8 * lb4) * 2));
            }
            #pragma unroll
            for (int nfp = 0; nfp < 2; nfp++) {
                uint32_t t4[4];
                const int row = wn + nfp * 16 + 8 * lb4 + l7;
                ldsm_x4(t4, Bbase + (uint32_t)(row * 144 + (ks * 16 + 8 * lb3) * 2));
                bf[2 * nfp][0] = t4[0]; bf[2 * nfp][1] = t4[1];
                bf[2 * nfp + 1][0] = t4[2]; bf[2 * nfp + 1][1] = t4[3];
            }
            #pragma unroll
            for (int mf = 0; mf < 4; mf++)
                #pragma unroll
                for (int nf = 0; nf < 4; nf++)
                    mma16(acc[mf][nf], af[mf], bf[nf]);
        }
    };

    ldg_async(0, 0); CPA_COMMIT(); CPA_WAIT0();
    __syncthreads();

    for (int kt = 0; kt < 32; kt++) {
        const int buf = kt & 1;
        if (kt < 31) { ldg_async(kt + 1, buf ^ 1); CPA_COMMIT(); }
        compute(buf);
        if (kt < 31) CPA_WAIT0();
        __syncthreads();
    }

    // epilogue
    #pragma unroll
    for (int mf = 0; mf < 4; mf++) {
        const int m = m0 + wm + mf * 16 + g;
        #pragma unroll
        for (int nf = 0; nf < 4; nf++) {
            const int n = n0 + wn + nf * 8 + 2 * q;
            const float b0v = bias[n], b1v = bias[n + 1];
            const float o0 = acc[mf][nf][0] + b0v, o1 = acc[mf][nf][1] + b1v;
            const float o2 = acc[mf][nf][2] + b0v, o3 = acc[mf][nf][3] + b1v;
            if (MODE == 0) {
                __half* out = (__half*)outp;
                const int b_ = m >> 10, s_ = m & (SS - 1);
                const int h_ = n >> 6, e_ = n & 63;
                __half* base = out + ((size_t)(b_ * HH + h_) * SS + s_) * HDIM + e_;
                *(uint32_t*)base = f2h2(o0, o1);
                *(uint32_t*)(base + 8 * HDIM) = f2h2(o2, o3);
            } else {
                float* out = (float*)outp;
                *(float2*)(out + (size_t)m * DD + n) = make_float2(o0, o1);
                *(float2*)(out + (size_t)(m + 8) * DD + n) = make_float2(o2, o3);
            }
        }
    }
}

__global__ __launch_bounds__(256, 2)
void proj_kernel(const float* __restrict__ bq, const float* __restrict__ bk,
                 const float* __restrict__ bv)
{
    const __half *X, *Wt;
    const float* bias;
    __half* out;
    const int z = blockIdx.z;
    X = g_Xh + (size_t)z * (BB * SS * DD);
    Wt = g_Wt + (size_t)z * DD * DD;
    if (z == 0)      { bias = bq; out = g_Q; }
    else if (z == 1) { bias = bk; out = g_K; }
    else             { bias = bv; out = g_V; }
    gemm_f16_body<0>(X, Wt, bias, out);
}

__global__ __launch_bounds__(256, 2)
void outproj_kernel(const float* __restrict__ bo, float* __restrict__ out)
{
    gemm_f16_body<1>(g_attn, g_Wot, bo, out);
}

// ---------------------------------------------------------------------------
// fp16 mma flash attention, register-resident P, cp.async 3-slot KV ring.
// CTA: 128 q rows of one (b,h); 8 warps; warp w owns rows 16w..16w+15.
// KV tiles of 64. K fragments via ldmatrix.x4 (nf pairs), V via x4.trans.
// ONE __syncthreads per tile (3-slot ring: slot (t+1)%3 last read at
// compute(t-2), fenced by sync(t-1) before the cp.async at iter t).
// Smem 55296 B: 3 slots x (K[64][72] + V[64][72]).  Q staged in slot 1.
// Masking identical to reference: masked logits += NEG (kept in denominator),
// numerator zeroed by mask bit.
// ---------------------------------------------------------------------------
__global__ __launch_bounds__(256, 2)
void attn_kernel()
{
    extern __shared__ __half hsm[];

    const int bh = blockIdx.y;
    const int b_ = bh >> 4, h_ = bh & 15;
    const int q0 = blockIdx.x * 128;

    const __half* Qp = g_Q + (size_t)bh * SS * HDIM;
    const __half* Kp = g_K + (size_t)bh * SS * HDIM;
    const __half* Vp = g_V + (size_t)bh * SS * HDIM;

    const int tid = threadIdx.x, lane = tid & 31, w = tid >> 5;
    const int g = lane >> 2, q = lane & 3;
    const int l7 = lane & 7, lb3 = (lane >> 3) & 1, lb4 = lane >> 4;
    const int row0 = 16 * w + g;
    const float scale = 0.03125f;

    const uint32_t sbase = smem_u32(hsm);
    // per-thread cp.async mapping for a 64x64 tile (512 chunks of 8 halves)
    const int cRow = tid >> 3, cC8 = (tid & 7) * 8;
    auto cpaKV = [&](int t0, int slot) {
        const uint32_t kb = sbase + slot * 18432;
        #pragma unroll
        for (int i = 0; i < 2; i++) {
            const int row = cRow + i * 32;
            const uint32_t off = (uint32_t)(row * 144 + cC8 * 2);
            cpa16(kb + off,        Kp + (size_t)(t0 + row) * HDIM + cC8);
            cpa16(kb + 9216 + off, Vp + (size_t)(t0 + row) * HDIM + cC8);
        }
    };

    // tile 0 in flight while Q stages into slot 1's region
    cpaKV(0, 0); CPA_COMMIT();

    __half* Qs = hsm + 9216;   // slot 1 region, 128x72 halves
    #pragma unroll
    for (int i = 0; i < 4; i++) {
        const int idx = tid + 256 * i;
        const int r = idx >> 3, c8 = (idx & 7) * 8;
        *(uint4*)&Qs[r * 72 + c8] = *(const uint4*)(Qp + (size_t)(q0 + r) * HDIM + c8);
    }
    __syncthreads();

    uint32_t qf[4][4];
    {
        const uint32_t qb = smem_u32(Qs);
        const int row = 16 * w + l7 + 8 * lb3;
        #pragma unroll
        for (int ks = 0; ks < 4; ks++)
            ldsm_x4(qf[ks], qb + (uint32_t)(row * 144 + (ks * 16 + 8 * lb4) * 2));
    }
    __syncthreads();   // Q hoist done; slot 1 may be overwritten

    float O[8][4];
    #pragma unroll
    for (int nf = 0; nf < 8; nf++)
        #pragma unroll
        for (int r = 0; r < 4; r++) O[nf][r] = 0.f;

    float mg = -1e30f, m8 = -1e30f, lg = 0.f, l8 = 0.f;

    const uint32_t* mrow  = g_mbits + ((size_t)b_ * SS + q0 + row0) * 32;
    const uint32_t* mrow8 = mrow + 8 * 32;

    // lane-constant parts of the K (x4) and V (x4.trans) ldmatrix addresses
    const uint32_t klane = (uint32_t)((lb4 * 8 + l7) * 144 + lb3 * 16);
    const uint32_t vlane = (uint32_t)((lb3 * 8 + l7) * 144 + lb4 * 16);

    for (int t0 = 0; t0 < SS; t0 += 64) {
        const int t = t0 >> 6;
        const int slot = t % 3;
        if (t + 1 < 16) { cpaKV(t0 + 64, (t + 1) % 3); CPA_COMMIT(); CPA_WAIT1(); }
        else            { CPA_WAIT0(); }
        __syncthreads();

        const uint32_t kbase = sbase + slot * 18432;
        const uint32_t vbase = kbase + 9216;

        const int wc = t0 >> 5;
        const uint64_t M0 = ((uint64_t)mrow[wc]  | ((uint64_t)mrow[wc + 1]  << 32)) >> (2 * q);
        const uint64_t M8 = ((uint64_t)mrow8[wc] | ((uint64_t)mrow8[wc + 1] << 32)) >> (2 * q);

        // ---- QK^T ----
        float s[8][4];
        #pragma unroll
        for (int nf = 0; nf < 8; nf++)
            #pragma unroll
            for (int r = 0; r < 4; r++) s[nf][r] = 0.f;

        #pragma unroll
        for (int ks = 0; ks < 4; ks++) {
            #pragma unroll
            for (int nf2 = 0; nf2 < 4; nf2++) {
                uint32_t t4[4];
                ldsm_x4(t4, kbase + (uint32_t)(nf2 * 2304 + ks * 32) + klane);
                mma16(s[2 * nf2],     qf[ks], t4);
                mma16(s[2 * nf2 + 1], qf[ks], t4 + 2);
            }
        }

        // ---- scale + mask bias, row max ----
        float rg = -1e30f, r8 = -1e30f;
        #pragma unroll
        for (int nf = 0; nf < 8; nf++) {
            const float fA0 = ((M0 >> (nf * 8)) & 1)     ? 0.f : NEGV;
            const float fB0 = ((M0 >> (nf * 8 + 1)) & 1) ? 0.f : NEGV;
            const float fA8 = ((M8 >> (nf * 8)) & 1)     ? 0.f : NEGV;
            const float fB8 = ((M8 >> (nf * 8 + 1)) & 1) ? 0.f : NEGV;
            s[nf][0] = s[nf][0] * scale + fA0;
            s[nf][1] = s[nf][1] * scale + fB0;
            s[nf][2] = s[nf][2] * scale + fA8;
            s[nf][3] = s[nf][3] * scale + fB8;
            rg = fmaxf(rg, fmaxf(s[nf][0], s[nf][1]));
            r8 = fmaxf(r8, fmaxf(s[nf][2], s[nf][3]));
        }
        rg = fmaxf(rg, __shfl_xor_sync(0xffffffffu, rg, 1));
        rg = fmaxf(rg, __shfl_xor_sync(0xffffffffu, rg, 2));
        r8 = fmaxf(r8, __shfl_xor_sync(0xffffffffu, r8, 1));
        r8 = fmaxf(r8, __shfl_xor_sync(0xffffffffu, r8, 2));

        const float mng = fmaxf(mg, rg), mn8 = fmaxf(m8, r8);
        const float ag = __expf(mg - mng), a8 = __expf(m8 - mn8);
        mg = mng; m8 = mn8;

        // ---- exp; denominator counts masked terms, numerator masked ----
        float sg = 0.f, s8sum = 0.f;
        #pragma unroll
        for (int nf = 0; nf < 8; nf++) {
            const float p0 = __expf(s[nf][0] - mg);
            const float p1 = __expf(s[nf][1] - mg);
            const float p2 = __expf(s[nf][2] - m8);
            const float p3 = __expf(s[nf][3] - m8);
            sg += p0 + p1; s8sum += p2 + p3;
            s[nf][0] = ((M0 >> (nf * 8)) & 1)     ? p0 : 0.f;
            s[nf][1] = ((M0 >> (nf * 8 + 1)) & 1) ? p1 : 0.f;
            s[nf][2] = ((M8 >> (nf * 8)) & 1)     ? p2 : 0.f;
            s[nf][3] = ((M8 >> (nf * 8 + 1)) & 1) ? p3 : 0.f;
            O[nf][0] *= ag; O[nf][1] *= ag;
            O[nf][2] *= a8; O[nf][3] *= a8;
        }
        sg    += __shfl_xor_sync(0xffffffffu, sg, 1);
        sg    += __shfl_xor_sync(0xffffffffu, sg, 2);
        s8sum += __shfl_xor_sync(0xffffffffu, s8sum, 1);
        s8sum += __shfl_xor_sync(0xffffffffu, s8sum, 2);
        lg = lg * ag + sg;
        l8 = l8 * a8 + s8sum;

        // ---- P @ V : P packed from registers (QK C-frag == PV A-frag) ----
        #pragma unroll
        for (int ks = 0; ks < 4; ks++) {
            uint32_t pf[4];
            pf[0] = f2h2(s[2 * ks][0],     s[2 * ks][1]);
            pf[1] = f2h2(s[2 * ks][2],     s[2 * ks][3]);
            pf[2] = f2h2(s[2 * ks + 1][0], s[2 * ks + 1][1]);
            pf[3] = f2h2(s[2 * ks + 1][2], s[2 * ks + 1][3]);
            #pragma unroll
            for (int nf2 = 0; nf2 < 4; nf2++) {
                uint32_t t4[4];
                ldsm_x4t(t4, vbase + (uint32_t)(ks * 2304 + nf2 * 32) + vlane);
                mma16(O[2 * nf2],     pf, t4);
                mma16(O[2 * nf2 + 1], pf, t4 + 2);
            }
        }
        // no trailing sync: next iter's cp.async targets slot (t+2)%3,
        // whose readers (compute t-1) finished before this iter's sync.
    }

    // ---- epilogue (fp16 out; rounding identical to outproj-side cvt) ----
    const float ig = 1.f / lg, i8 = 1.f / l8;
    __half* orow  = g_attn + (size_t)(b_ * SS + q0 + row0) * DD + h_ * HDIM;
    __half* orow8 = orow + 8 * DD;
    #pragma unroll
    for (int nf = 0; nf < 8; nf++) {
        const int e = nf * 8 + 2 * q;
        *(uint32_t*)(orow  + e) = f2h2(O[nf][0] * ig, O[nf][1] * ig);
        *(uint32_t*)(orow8 + e) = f2h2(O[nf][2] * i8, O[nf][3] * i8);
    }
}

// ---------------------------------------------------------------------------
extern "C" void kernel_launch(void* const* d_in, const int* in_sizes, int n_in,
                              void* d_out, int out_size)
{
    const float* q    = (const float*)d_in[0];
    const float* k    = (const float*)d_in[1];
    const float* v    = (const float*)d_in[2];
    const int*   mask = (const int*)  d_in[3];
    const float* Wq   = (const float*)d_in[4];
    const float* bq   = (const float*)d_in[5];
    const float* Wk   = (const float*)d_in[6];
    const float* bk   = (const float*)d_in[7];
    const float* Wv   = (const float*)d_in[8];
    const float* bv   = (const float*)d_in[9];
    const float* Wo   = (const float*)d_in[10];
    const float* bo   = (const float*)d_in[11];
    float* out = (float*)d_out;

    cudaFuncSetAttribute(proj_kernel,
                         cudaFuncAttributeMaxDynamicSharedMemorySize, 73728);
    cudaFuncSetAttribute(outproj_kernel,
                         cudaFuncAttributeMaxDynamicSharedMemorySize, 73728);
    cudaFuncSetAttribute(attn_kernel,
                         cudaFuncAttributeMaxDynamicSharedMemorySize, 55296);

    maskbits_kernel<<<BB * SS * (SS / 32) / 8, 256>>>(mask);

    x2h_kernel<<<dim3(BB * SS * DD / 2048, 1, 3), 256>>>(q, k, v);

    transpose_w<<<dim3(32, 32, 4), 256>>>(Wq, Wk, Wv, Wo);

    dim3 g1(8, 32, 3);                 // N/128, M/128, {Q,K,V}
    proj_kernel<<<g1, 256, 73728>>>(bq, bk, bv);

    dim3 g2(8, 64);                    // S/128 q-tiles, B*H
    attn_kernel<<<g2, 256, 55296>>>();

    dim3 g3(8, 32);                    // N/128, M/128
    outproj_kernel<<<g3, 256, 73728>>>(bo, out);
}

// round 13
// speedup vs baseline: 5.7336x; 1.0110x over previous
#include <cuda_runtime.h>
#include <cuda_fp16.h>
#include <math.h>
#include <stdint.h>

#define BB 4
#define SS 1024
#define DD 1024
#define HH 16
#define HDIM 64
#define NEGV -10000000000.0f

// Scratch (module-load allocated; no runtime allocs)
__device__ __half g_Xh[3*BB*SS*DD];           // Xq/Xk/Xv pre-converted to fp16
__device__ __half g_Q[BB*HH*SS*HDIM];
__device__ __half g_K[BB*HH*SS*HDIM];
__device__ __half g_V[BB*HH*SS*HDIM];
__device__ __half g_attn[BB*SS*DD];
__device__ uint32_t g_mbits[BB*SS*(SS/32)];   // packed mask bits
__device__ __half g_Wt[3*DD*DD];              // Wq/Wk/Wv transposed to [n][k], fp16
__device__ __half g_Wot[DD*DD];               // Wo transposed to [n][k], fp16

// ---------------------------------------------------------------------------
// helpers
// ---------------------------------------------------------------------------
__device__ __forceinline__ uint32_t f2h2(float lo, float hi) {
    __half2 h = __floats2half2_rn(lo, hi);
    return *reinterpret_cast<uint32_t*>(&h);
}

__device__ __forceinline__ void mma16(float* c, const uint32_t* a, const uint32_t* b) {
    asm volatile(
        "mma.sync.aligned.m16n8k16.row.col.f32.f16.f16.f32 "
        "{%0,%1,%2,%3}, {%4,%5,%6,%7}, {%8,%9}, {%0,%1,%2,%3};"
        : "+f"(c[0]), "+f"(c[1]), "+f"(c[2]), "+f"(c[3])
        : "r"(a[0]), "r"(a[1]), "r"(a[2]), "r"(a[3]), "r"(b[0]), "r"(b[1]));
}

__device__ __forceinline__ uint32_t smem_u32(const void* p) {
    uint32_t a;
    asm("{ .reg .u64 t; cvta.to.shared.u64 t, %1; cvt.u32.u64 %0, t; }"
        : "=r"(a) : "l"(p));
    return a;
}

__device__ __forceinline__ void ldsm_x4(uint32_t* r, uint32_t a) {
    asm volatile("ldmatrix.sync.aligned.m8n8.x4.shared.b16 {%0,%1,%2,%3}, [%4];"
        : "=r"(r[0]), "=r"(r[1]), "=r"(r[2]), "=r"(r[3]) : "r"(a));
}
__device__ __forceinline__ void ldsm_x4t(uint32_t* r, uint32_t a) {
    asm volatile("ldmatrix.sync.aligned.m8n8.x4.trans.shared.b16 {%0,%1,%2,%3}, [%4];"
        : "=r"(r[0]), "=r"(r[1]), "=r"(r[2]), "=r"(r[3]) : "r"(a));
}

__device__ __forceinline__ void cpa16(uint32_t dst, const void* src) {
    asm volatile("cp.async.cg.shared.global [%0], [%1], 16;" :: "r"(dst), "l"(src));
}
#define CPA_COMMIT() asm volatile("cp.async.commit_group;")
#define CPA_WAIT0()  asm volatile("cp.async.wait_group 0;")
#define CPA_WAIT1()  asm volatile("cp.async.wait_group 1;")

// ---------------------------------------------------------------------------
// Prepass kernels
// ---------------------------------------------------------------------------
__global__ __launch_bounds__(256)
void maskbits_kernel(const int* __restrict__ mask)
{
    const int widx = blockIdx.x * 8 + (threadIdx.x >> 5);
    const int lanev = mask[(size_t)widx * 32 + (threadIdx.x & 31)];
    const uint32_t bal = __ballot_sync(0xffffffffu, lanev != 0);
    if ((threadIdx.x & 31) == 0) g_mbits[widx] = bal;
}

// fp32 -> fp16 conversion of the three X inputs.
__global__ __launch_bounds__(256)
void x2h_kernel(const float* __restrict__ Xq, const float* __restrict__ Xk,
                const float* __restrict__ Xv)
{
    const int z = blockIdx.z;
    const float* src = (z == 0) ? Xq : (z == 1) ? Xk : Xv;
    __half* dst = g_Xh + (size_t)z * (BB * SS * DD);
    const size_t i8 = ((size_t)blockIdx.x * 256 + threadIdx.x) * 8;
    float4 a = *(const float4*)(src + i8);
    float4 b = *(const float4*)(src + i8 + 4);
    uint4 o;
    o.x = f2h2(a.x, a.y); o.y = f2h2(a.z, a.w);
    o.z = f2h2(b.x, b.y); o.w = f2h2(b.z, b.w);
    *(uint4*)(dst + i8) = o;
}

// Weight transpose -> [n][k] fp16 scratch.
__global__ __launch_bounds__(256)
void transpose_w(const float* __restrict__ Wq, const float* __restrict__ Wk,
                 const float* __restrict__ Wv, const float* __restrict__ Wo)
{
    __shared__ float t[32][33];
    const int z = blockIdx.z;
    const float* W = (z == 0) ? Wq : (z == 1) ? Wk : (z == 2) ? Wv : Wo;
    __half* out = (z < 3) ? (g_Wt + (size_t)z * DD * DD) : g_Wot;
    const int n0 = blockIdx.x * 32, k0 = blockIdx.y * 32;
    const int tx = threadIdx.x & 31, ty = threadIdx.x >> 5;

    #pragma unroll
    for (int j = 0; j < 4; j++) {
        const int k = k0 + ty + 8 * j;
        const int n = n0 + tx;
        const float v = (z < 3)
            ? W[(size_t)(n >> 6) * (DD * HDIM) + (size_t)k * HDIM + (n & 63)]
            : W[(size_t)k * DD + n];
        t[ty + 8 * j][tx] = v;
    }
    __syncthreads();
    #pragma unroll
    for (int j = 0; j < 4; j++) {
        const int n = n0 + ty + 8 * j;
        const int k = k0 + tx;
        out[(size_t)n * DD + k] = __float2half_rn(t[tx][ty + 8 * j]);
    }
}

// ---------------------------------------------------------------------------
// fp16 GEMM: C[4096,1024] = X @ Wt^T + bias, X and Wt already fp16.
// 128x128x32 tiles, cp.async 3-SLOT RING with wait_group 1 (R12 fix: the old
// 2-stage code did wait_group 0 on the just-issued load -> exposed full LDG
// latency every k-tile; now we only wait for the load issued one iteration
// ago). Slot reuse safety: cpa(kt+1) targets slot (kt+1)%3 = (kt-2)%3, last
// read by compute(kt-2), separated by the __syncthreads inside iter kt-1.
// 8 warps of 64x32, m16n8k16 via ldmatrix, rows stride 72 halves (144B).
// dyn smem: 3 slots x (A[128][72] + B[128][72]) = 110592 B (2 CTAs/SM).
// ---------------------------------------------------------------------------
template<int MODE>
__device__ __forceinline__ void gemm_f16_body(const __half* __restrict__ X,
                                              const __half* __restrict__ Wt,
                                              const float* __restrict__ bias,
                                              void* __restrict__ outp)
{
    extern __shared__ __half hsm[];
    const int tid = threadIdx.x, lane = tid & 31, w = tid >> 5;
    const int g = lane >> 2, q = lane & 3;
    const int l7 = lane & 7, lb3 = (lane >> 3) & 1, lb4 = lane >> 4;
    const int wm = (w >> 2) * 64, wn = (w & 3) * 32;
    const int m0 = blockIdx.y * 128, n0 = blockIdx.x * 128;
    const uint32_t sbase = smem_u32(hsm);

    float acc[4][4][4];
    #pragma unroll
    for (int i = 0; i < 4; i++)
        #pragma unroll
        for (int j = 0; j < 4; j++)
            #pragma unroll
            for (int r = 0; r < 4; r++) acc[i][j][r] = 0.f;

    const int ldRow = tid >> 2, ldC8 = (tid & 3) * 8;

    auto ldg_async = [&](int kt, int slot) {
        const int kb = kt * 32;
        const uint32_t abase = sbase + slot * 36864;
        #pragma unroll
        for (int i = 0; i < 2; i++) {
            const int row = ldRow + i * 64;
            const uint32_t off = (uint32_t)(row * 144 + ldC8 * 2);
            cpa16(abase + off,         X  + (size_t)(m0 + row) * DD + kb + ldC8);
            cpa16(abase + 18432 + off, Wt + (size_t)(n0 + row) * DD + kb + ldC8);
        }
    };

    auto compute = [&](int slot) {
        const uint32_t Abase = sbase + slot * 36864;
        const uint32_t Bbase = Abase + 18432;
        #pragma unroll
        for (int ks = 0; ks < 2; ks++) {
            uint32_t af[4][4], bf[4][2];
            #pragma unroll
            for (int mf = 0; mf < 4; mf++) {
                const int row = wm + mf * 16 + l7 + 8 * lb3;
                ldsm_x4(af[mf], Abase + (uint32_t)(row * 144 + (ks * 16 + 8 * lb4) * 2));
            }
            #pragma unroll
            for (int nfp = 0; nfp < 2; nfp++) {
                uint32_t t4[4];
                const int row = wn + nfp * 16 + 8 * lb4 + l7;
                ldsm_x4(t4, Bbase + (uint32_t)(row * 144 + (ks * 16 + 8 * lb3) * 2));
                bf[2 * nfp][0] = t4[0]; bf[2 * nfp][1] = t4[1];
                bf[2 * nfp + 1][0] = t4[2]; bf[2 * nfp + 1][1] = t4[3];
            }
            #pragma unroll
            for (int mf = 0; mf < 4; mf++)
                #pragma unroll
                for (int nf = 0; nf < 4; nf++)
                    mma16(acc[mf][nf], af[mf], bf[nf]);
        }
    };

    ldg_async(0, 0); CPA_COMMIT();

    for (int kt = 0; kt < 32; kt++) {
        const int slot = kt % 3;
        if (kt < 31) { ldg_async(kt + 1, (kt + 1) % 3); CPA_COMMIT(); CPA_WAIT1(); }
        else         { CPA_WAIT0(); }
        __syncthreads();
        compute(slot);
        // no trailing sync: next iter's cpa targets slot (kt+2)%3, whose
        // readers (compute kt-1) finished before this iter's sync.
    }

    // epilogue
    #pragma unroll
    for (int mf = 0; mf < 4; mf++) {
        const int m = m0 + wm + mf * 16 + g;
        #pragma unroll
        for (int nf = 0; nf < 4; nf++) {
            const int n = n0 + wn + nf * 8 + 2 * q;
            const float b0v = bias[n], b1v = bias[n + 1];
            const float o0 = acc[mf][nf][0] + b0v, o1 = acc[mf][nf][1] + b1v;
            const float o2 = acc[mf][nf][2] + b0v, o3 = acc[mf][nf][3] + b1v;
            if (MODE == 0) {
                __half* out = (__half*)outp;
                const int b_ = m >> 10, s_ = m & (SS - 1);
                const int h_ = n >> 6, e_ = n & 63;
                __half* base = out + ((size_t)(b_ * HH + h_) * SS + s_) * HDIM + e_;
                *(uint32_t*)base = f2h2(o0, o1);
                *(uint32_t*)(base + 8 * HDIM) = f2h2(o2, o3);
            } else {
                float* out = (float*)outp;
                *(float2*)(out + (size_t)m * DD + n) = make_float2(o0, o1);
                *(float2*)(out + (size_t)(m + 8) * DD + n) = make_float2(o2, o3);
            }
        }
    }
}

__global__ __launch_bounds__(256, 2)
void proj_kernel(const float* __restrict__ bq, const float* __restrict__ bk,
                 const float* __restrict__ bv)
{
    const __half *X, *Wt;
    const float* bias;
    __half* out;
    const int z = blockIdx.z;
    X = g_Xh + (size_t)z * (BB * SS * DD);
    Wt = g_Wt + (size_t)z * DD * DD;
    if (z == 0)      { bias = bq; out = g_Q; }
    else if (z == 1) { bias = bk; out = g_K; }
    else             { bias = bv; out = g_V; }
    gemm_f16_body<0>(X, Wt, bias, out);
}

__global__ __launch_bounds__(256, 2)
void outproj_kernel(const float* __restrict__ bo, float* __restrict__ out)
{
    gemm_f16_body<1>(g_attn, g_Wot, bo, out);
}

// ---------------------------------------------------------------------------
// fp16 mma flash attention (unchanged from R11 — passing at 5.167e-4).
// Register-resident P, cp.async 3-slot KV ring, x4 ldmatrix fragments.
// ---------------------------------------------------------------------------
__global__ __launch_bounds__(256, 2)
void attn_kernel()
{
    extern __shared__ __half hsm[];

    const int bh = blockIdx.y;
    const int b_ = bh >> 4, h_ = bh & 15;
    const int q0 = blockIdx.x * 128;

    const __half* Qp = g_Q + (size_t)bh * SS * HDIM;
    const __half* Kp = g_K + (size_t)bh * SS * HDIM;
    const __half* Vp = g_V + (size_t)bh * SS * HDIM;

    const int tid = threadIdx.x, lane = tid & 31, w = tid >> 5;
    const int g = lane >> 2, q = lane & 3;
    const int l7 = lane & 7, lb3 = (lane >> 3) & 1, lb4 = lane >> 4;
    const int row0 = 16 * w + g;
    const float scale = 0.03125f;

    const uint32_t sbase = smem_u32(hsm);
    const int cRow = tid >> 3, cC8 = (tid & 7) * 8;
    auto cpaKV = [&](int t0, int slot) {
        const uint32_t kb = sbase + slot * 18432;
        #pragma unroll
        for (int i = 0; i < 2; i++) {
            const int row = cRow + i * 32;
            const uint32_t off = (uint32_t)(row * 144 + cC8 * 2);
            cpa16(kb + off,        Kp + (size_t)(t0 + row) * HDIM + cC8);
            cpa16(kb + 9216 + off, Vp + (size_t)(t0 + row) * HDIM + cC8);
        }
    };

    cpaKV(0, 0); CPA_COMMIT();

    __half* Qs = hsm + 9216;   // slot 1 region, 128x72 halves
    #pragma unroll
    for (int i = 0; i < 4; i++) {
        const int idx = tid + 256 * i;
        const int r = idx >> 3, c8 = (idx & 7) * 8;
        *(uint4*)&Qs[r * 72 + c8] = *(const uint4*)(Qp + (size_t)(q0 + r) * HDIM + c8);
    }
    __syncthreads();

    uint32_t qf[4][4];
    {
        const uint32_t qb = smem_u32(Qs);
        const int row = 16 * w + l7 + 8 * lb3;
        #pragma unroll
        for (int ks = 0; ks < 4; ks++)
            ldsm_x4(qf[ks], qb + (uint32_t)(row * 144 + (ks * 16 + 8 * lb4) * 2));
    }
    __syncthreads();   // Q hoist done; slot 1 may be overwritten

    float O[8][4];
    #pragma unroll
    for (int nf = 0; nf < 8; nf++)
        #pragma unroll
        for (int r = 0; r < 4; r++) O[nf][r] = 0.f;

    float mg = -1e30f, m8 = -1e30f, lg = 0.f, l8 = 0.f;

    const uint32_t* mrow  = g_mbits + ((size_t)b_ * SS + q0 + row0) * 32;
    const uint32_t* mrow8 = mrow + 8 * 32;

    const uint32_t klane = (uint32_t)((lb4 * 8 + l7) * 144 + lb3 * 16);
    const uint32_t vlane = (uint32_t)((lb3 * 8 + l7) * 144 + lb4 * 16);

    for (int t0 = 0; t0 < SS; t0 += 64) {
        const int t = t0 >> 6;
        const int slot = t % 3;
        if (t + 1 < 16) { cpaKV(t0 + 64, (t + 1) % 3); CPA_COMMIT(); CPA_WAIT1(); }
        else            { CPA_WAIT0(); }
        __syncthreads();

        const uint32_t kbase = sbase + slot * 18432;
        const uint32_t vbase = kbase + 9216;

        const int wc = t0 >> 5;
        const uint64_t M0 = ((uint64_t)mrow[wc]  | ((uint64_t)mrow[wc + 1]  << 32)) >> (2 * q);
        const uint64_t M8 = ((uint64_t)mrow8[wc] | ((uint64_t)mrow8[wc + 1] << 32)) >> (2 * q);

        // ---- QK^T ----
        float s[8][4];
        #pragma unroll
        for (int nf = 0; nf < 8; nf++)
            #pragma unroll
            for (int r = 0; r < 4; r++) s[nf][r] = 0.f;

        #pragma unroll
        for (int ks = 0; ks < 4; ks++) {
            #pragma unroll
            for (int nf2 = 0; nf2 < 4; nf2++) {
                uint32_t t4[4];
                ldsm_x4(t4, kbase + (uint32_t)(nf2 * 2304 + ks * 32) + klane);
                mma16(s[2 * nf2],     qf[ks], t4);
                mma16(s[2 * nf2 + 1], qf[ks], t4 + 2);
            }
        }

        // ---- scale + mask bias, row max ----
        float rg = -1e30f, r8 = -1e30f;
        #pragma unroll
        for (int nf = 0; nf < 8; nf++) {
            const float fA0 = ((M0 >> (nf * 8)) & 1)     ? 0.f : NEGV;
            const float fB0 = ((M0 >> (nf * 8 + 1)) & 1) ? 0.f : NEGV;
            const float fA8 = ((M8 >> (nf * 8)) & 1)     ? 0.f : NEGV;
            const float fB8 = ((M8 >> (nf * 8 + 1)) & 1) ? 0.f : NEGV;
            s[nf][0] = s[nf][0] * scale + fA0;
            s[nf][1] = s[nf][1] * scale + fB0;
            s[nf][2] = s[nf][2] * scale + fA8;
            s[nf][3] = s[nf][3] * scale + fB8;
            rg = fmaxf(rg, fmaxf(s[nf][0], s[nf][1]));
            r8 = fmaxf(r8, fmaxf(s[nf][2], s[nf][3]));
        }
        rg = fmaxf(rg, __shfl_xor_sync(0xffffffffu, rg, 1));
        rg = fmaxf(rg, __shfl_xor_sync(0xffffffffu, rg, 2));
        r8 = fmaxf(r8, __shfl_xor_sync(0xffffffffu, r8, 1));
        r8 = fmaxf(r8, __shfl_xor_sync(0xffffffffu, r8, 2));

        const float mng = fmaxf(mg, rg), mn8 = fmaxf(m8, r8);
        const float ag = __expf(mg - mng), a8 = __expf(m8 - mn8);
        mg = mng; m8 = mn8;

        // ---- exp; denominator counts masked terms, numerator masked ----
        float sg = 0.f, s8sum = 0.f;
        #pragma unroll
        for (int nf = 0; nf < 8; nf++) {
            const float p0 = __expf(s[nf][0] - mg);
            const float p1 = __expf(s[nf][1] - mg);
            const float p2 = __expf(s[nf][2] - m8);
            const float p3 = __expf(s[nf][3] - m8);
            sg += p0 + p1; s8sum += p2 + p3;
            s[nf][0] = ((M0 >> (nf * 8)) & 1)     ? p0 : 0.f;
            s[nf][1] = ((M0 >> (nf * 8 + 1)) & 1) ? p1 : 0.f;
            s[nf][2] = ((M8 >> (nf * 8)) & 1)     ? p2 : 0.f;
            s[nf][3] = ((M8 >> (nf * 8 + 1)) & 1) ? p3 : 0.f;
            O[nf][0] *= ag; O[nf][1] *= ag;
            O[nf][2] *= a8; O[nf][3] *= a8;
        }
        sg    += __shfl_xor_sync(0xffffffffu, sg, 1);
        sg    += __shfl_xor_sync(0xffffffffu, sg, 2);
        s8sum += __shfl_xor_sync(0xffffffffu, s8sum, 1);
        s8sum += __shfl_xor_sync(0xffffffffu, s8sum, 2);
        lg = lg * ag + sg;
        l8 = l8 * a8 + s8sum;

        // ---- P @ V : P packed from registers (QK C-frag == PV A-frag) ----
        #pragma unroll
        for (int ks = 0; ks < 4; ks++) {
            uint32_t pf[4];
            pf[0] = f2h2(s[2 * ks][0],     s[2 * ks][1]);
            pf[1] = f2h2(s[2 * ks][2],     s[2 * ks][3]);
            pf[2] = f2h2(s[2 * ks + 1][0], s[2 * ks + 1][1]);
            pf[3] = f2h2(s[2 * ks + 1][2], s[2 * ks + 1][3]);
            #pragma unroll
            for (int nf2 = 0; nf2 < 4; nf2++) {
                uint32_t t4[4];
                ldsm_x4t(t4, vbase + (uint32_t)(ks * 2304 + nf2 * 32) + vlane);
                mma16(O[2 * nf2],     pf, t4);
                mma16(O[2 * nf2 + 1], pf, t4 + 2);
            }
        }
    }

    // ---- epilogue ----
    const float ig = 1.f / lg, i8 = 1.f / l8;
    __half* orow  = g_attn + (size_t)(b_ * SS + q0 + row0) * DD + h_ * HDIM;
    __half* orow8 = orow + 8 * DD;
    #pragma unroll
    for (int nf = 0; nf < 8; nf++) {
        const int e = nf * 8 + 2 * q;
        *(uint32_t*)(orow  + e) = f2h2(O[nf][0] * ig, O[nf][1] * ig);
        *(uint32_t*)(orow8 + e) = f2h2(O[nf][2] * i8, O[nf][3] * i8);
    }
}

// ---------------------------------------------------------------------------
extern "C" void kernel_launch(void* const* d_in, const int* in_sizes, int n_in,
                              void* d_out, int out_size)
{
    const float* q    = (const float*)d_in[0];
    const float* k    = (const float*)d_in[1];
    const float* v    = (const float*)d_in[2];
    const int*   mask = (const int*)  d_in[3];
    const float* Wq   = (const float*)d_in[4];
    const float* bq   = (const float*)d_in[5];
    const float* Wk   = (const float*)d_in[6];
    const float* bk   = (const float*)d_in[7];
    const float* Wv   = (const float*)d_in[8];
    const float* bv   = (const float*)d_in[9];
    const float* Wo   = (const float*)d_in[10];
    const float* bo   = (const float*)d_in[11];
    float* out = (float*)d_out;

    cudaFuncSetAttribute(proj_kernel,
                         cudaFuncAttributeMaxDynamicSharedMemorySize, 110592);
    cudaFuncSetAttribute(outproj_kernel,
                         cudaFuncAttributeMaxDynamicSharedMemorySize, 110592);
    cudaFuncSetAttribute(attn_kernel,
                         cudaFuncAttributeMaxDynamicSharedMemorySize, 55296);

    maskbits_kernel<<<BB * SS * (SS / 32) / 8, 256>>>(mask);

    x2h_kernel<<<dim3(BB * SS * DD / 2048, 1, 3), 256>>>(q, k, v);

    transpose_w<<<dim3(32, 32, 4), 256>>>(Wq, Wk, Wv, Wo);

    dim3 g1(8, 32, 3);                 // N/128, M/128, {Q,K,V}
    proj_kernel<<<g1, 256, 110592>>>(bq, bk, bv);

    dim3 g2(8, 64);                    // S/128 q-tiles, B*H
    attn_kernel<<<g2, 256, 55296>>>();

    dim3 g3(8, 32);                    // N/128, M/128
    outproj_kernel<<<g3, 256, 110592>>>(bo, out);
}

// round 14
// speedup vs baseline: 6.1313x; 1.0694x over previous
#include <cuda_runtime.h>
#include <cuda_fp16.h>
#include <math.h>
#include <stdint.h>

#define BB 4
#define SS 1024
#define DD 1024
#define HH 16
#define HDIM 64

// log2-domain softmax constants: p = 2^(dot*SC + NEGL - m)  ==  exp(dot*scale + NEG - m)
#define SC_LOG2  0.04508422003f      // (1/32) * log2(e)
#define NEGL     -1.44269504e10f     // -1e10  * log2(e)

// Scratch (module-load allocated; no runtime allocs)
__device__ __half g_Xh[3*BB*SS*DD];           // Xq/Xk/Xv pre-converted to fp16
__device__ __half g_Q[BB*HH*SS*HDIM];
__device__ __half g_K[BB*HH*SS*HDIM];
__device__ __half g_V[BB*HH*SS*HDIM];
__device__ __half g_attn[BB*SS*DD];
__device__ uint32_t g_mbits[BB*SS*(SS/32)];   // packed mask bits
__device__ __half g_Wt[3*DD*DD];              // Wq/Wk/Wv transposed to [n][k], fp16
__device__ __half g_Wot[DD*DD];               // Wo transposed to [n][k], fp16

// ---------------------------------------------------------------------------
// helpers
// ---------------------------------------------------------------------------
__device__ __forceinline__ uint32_t f2h2(float lo, float hi) {
    __half2 h = __floats2half2_rn(lo, hi);
    return *reinterpret_cast<uint32_t*>(&h);
}

__device__ __forceinline__ float ex2(float x) {
    float y;
    asm("ex2.approx.f32 %0, %1;" : "=f"(y) : "f"(x));
    return y;
}

__device__ __forceinline__ void mma16(float* c, const uint32_t* a, const uint32_t* b) {
    asm volatile(
        "mma.sync.aligned.m16n8k16.row.col.f32.f16.f16.f32 "
        "{%0,%1,%2,%3}, {%4,%5,%6,%7}, {%8,%9}, {%0,%1,%2,%3};"
        : "+f"(c[0]), "+f"(c[1]), "+f"(c[2]), "+f"(c[3])
        : "r"(a[0]), "r"(a[1]), "r"(a[2]), "r"(a[3]), "r"(b[0]), "r"(b[1]));
}

__device__ __forceinline__ uint32_t smem_u32(const void* p) {
    uint32_t a;
    asm("{ .reg .u64 t; cvta.to.shared.u64 t, %1; cvt.u32.u64 %0, t; }"
        : "=r"(a) : "l"(p));
    return a;
}

__device__ __forceinline__ void ldsm_x4(uint32_t* r, uint32_t a) {
    asm volatile("ldmatrix.sync.aligned.m8n8.x4.shared.b16 {%0,%1,%2,%3}, [%4];"
        : "=r"(r[0]), "=r"(r[1]), "=r"(r[2]), "=r"(r[3]) : "r"(a));
}
__device__ __forceinline__ void ldsm_x4t(uint32_t* r, uint32_t a) {
    asm volatile("ldmatrix.sync.aligned.m8n8.x4.trans.shared.b16 {%0,%1,%2,%3}, [%4];"
        : "=r"(r[0]), "=r"(r[1]), "=r"(r[2]), "=r"(r[3]) : "r"(a));
}

__device__ __forceinline__ void cpa16(uint32_t dst, const void* src) {
    asm volatile("cp.async.cg.shared.global [%0], [%1], 16;" :: "r"(dst), "l"(src));
}
#define CPA_COMMIT() asm volatile("cp.async.commit_group;")
#define CPA_WAIT0()  asm volatile("cp.async.wait_group 0;")
#define CPA_WAIT1()  asm volatile("cp.async.wait_group 1;")

// ---------------------------------------------------------------------------
// Prepass kernels
// ---------------------------------------------------------------------------
__global__ __launch_bounds__(256)
void maskbits_kernel(const int* __restrict__ mask)
{
    const int widx = blockIdx.x * 8 + (threadIdx.x >> 5);
    const int lanev = mask[(size_t)widx * 32 + (threadIdx.x & 31)];
    const uint32_t bal = __ballot_sync(0xffffffffu, lanev != 0);
    if ((threadIdx.x & 31) == 0) g_mbits[widx] = bal;
}

__global__ __launch_bounds__(256)
void x2h_kernel(const float* __restrict__ Xq, const float* __restrict__ Xk,
                const float* __restrict__ Xv)
{
    const int z = blockIdx.z;
    const float* src = (z == 0) ? Xq : (z == 1) ? Xk : Xv;
    __half* dst = g_Xh + (size_t)z * (BB * SS * DD);
    const size_t i8 = ((size_t)blockIdx.x * 256 + threadIdx.x) * 8;
    float4 a = *(const float4*)(src + i8);
    float4 b = *(const float4*)(src + i8 + 4);
    uint4 o;
    o.x = f2h2(a.x, a.y); o.y = f2h2(a.z, a.w);
    o.z = f2h2(b.x, b.y); o.w = f2h2(b.z, b.w);
    *(uint4*)(dst + i8) = o;
}

__global__ __launch_bounds__(256)
void transpose_w(const float* __restrict__ Wq, const float* __restrict__ Wk,
                 const float* __restrict__ Wv, const float* __restrict__ Wo)
{
    __shared__ float t[32][33];
    const int z = blockIdx.z;
    const float* W = (z == 0) ? Wq : (z == 1) ? Wk : (z == 2) ? Wv : Wo;
    __half* out = (z < 3) ? (g_Wt + (size_t)z * DD * DD) : g_Wot;
    const int n0 = blockIdx.x * 32, k0 = blockIdx.y * 32;
    const int tx = threadIdx.x & 31, ty = threadIdx.x >> 5;

    #pragma unroll
    for (int j = 0; j < 4; j++) {
        const int k = k0 + ty + 8 * j;
        const int n = n0 + tx;
        const float v = (z < 3)
            ? W[(size_t)(n >> 6) * (DD * HDIM) + (size_t)k * HDIM + (n & 63)]
            : W[(size_t)k * DD + n];
        t[ty + 8 * j][tx] = v;
    }
    __syncthreads();
    #pragma unroll
    for (int j = 0; j < 4; j++) {
        const int n = n0 + ty + 8 * j;
        const int k = k0 + tx;
        out[(size_t)n * DD + k] = __float2half_rn(t[tx][ty + 8 * j]);
    }
}

// ---------------------------------------------------------------------------
// fp16 GEMM: C[4096,1024] = X @ Wt^T + bias, X and Wt already fp16.
// R13: BK=64 (was 32) at the SAME smem footprint — the old layout wasted half
// of each 144B row (32 halves data + 40 pad). Now rows carry 64 halves + 8
// pad. k-tiles 32 -> 16: half the barriers/waits, each wait covered by ~2x
// more compute. 3-slot cp.async ring, wait_group 1. 8 warps of 64x32,
// m16n8k16 via ldmatrix (ks 0..3, max frag offset 112B < 144B row).
// dyn smem: 3 slots x (A[128][72] + B[128][72]) = 110592 B (2 CTAs/SM).
// ---------------------------------------------------------------------------
template<int MODE>
__device__ __forceinline__ void gemm_f16_body(const __half* __restrict__ X,
                                              const __half* __restrict__ Wt,
                                              const float* __restrict__ bias,
                                              void* __restrict__ outp)
{
    extern __shared__ __half hsm[];
    const int tid = threadIdx.x, lane = tid & 31, w = tid >> 5;
    const int g = lane >> 2, q = lane & 3;
    const int l7 = lane & 7, lb3 = (lane >> 3) & 1, lb4 = lane >> 4;
    const int wm = (w >> 2) * 64, wn = (w & 3) * 32;
    const int m0 = blockIdx.y * 128, n0 = blockIdx.x * 128;
    const uint32_t sbase = smem_u32(hsm);

    float acc[4][4][4];
    #pragma unroll
    for (int i = 0; i < 4; i++)
        #pragma unroll
        for (int j = 0; j < 4; j++)
            #pragma unroll
            for (int r = 0; r < 4; r++) acc[i][j][r] = 0.f;

    auto ldg_async = [&](int kt, int slot) {
        const int kb = kt * 64;
        const uint32_t abase = sbase + slot * 36864;
        #pragma unroll
        for (int i = 0; i < 4; i++) {
            const int idx = tid + 256 * i;
            const int row = idx >> 3, c8 = (idx & 7) * 8;
            const uint32_t off = (uint32_t)(row * 144 + c8 * 2);
            cpa16(abase + off,         X  + (size_t)(m0 + row) * DD + kb + c8);
            cpa16(abase + 18432 + off, Wt + (size_t)(n0 + row) * DD + kb + c8);
        }
    };

    auto compute = [&](int slot) {
        const uint32_t Abase = sbase + slot * 36864;
        const uint32_t Bbase = Abase + 18432;
        #pragma unroll
        for (int ks = 0; ks < 4; ks++) {
            uint32_t af[4][4], bf[4][2];
            #pragma unroll
            for (int mf = 0; mf < 4; mf++) {
                const int row = wm + mf * 16 + l7 + 8 * lb3;
                ldsm_x4(af[mf], Abase + (uint32_t)(row * 144 + (ks * 16 + 8 * lb4) * 2));
            }
            #pragma unroll
            for (int nfp = 0; nfp < 2; nfp++) {
                uint32_t t4[4];
                const int row = wn + nfp * 16 + 8 * lb4 + l7;
                ldsm_x4(t4, Bbase + (uint32_t)(row * 144 + (ks * 16 + 8 * lb3) * 2));
                bf[2 * nfp][0] = t4[0]; bf[2 * nfp][1] = t4[1];
                bf[2 * nfp + 1][0] = t4[2]; bf[2 * nfp + 1][1] = t4[3];
            }
            #pragma unroll
            for (int mf = 0; mf < 4; mf++)
                #pragma unroll
                for (int nf = 0; nf < 4; nf++)
                    mma16(acc[mf][nf], af[mf], bf[nf]);
        }
    };

    ldg_async(0, 0); CPA_COMMIT();

    for (int kt = 0; kt < 16; kt++) {
        const int slot = kt % 3;
        if (kt < 15) { ldg_async(kt + 1, (kt + 1) % 3); CPA_COMMIT(); CPA_WAIT1(); }
        else         { CPA_WAIT0(); }
        __syncthreads();
        compute(slot);
        // next iter's cpa targets slot (kt+2)%3, whose readers (compute kt-1)
        // finished before this iter's sync -> WAR safe.
    }

    // epilogue
    #pragma unroll
    for (int mf = 0; mf < 4; mf++) {
        const int m = m0 + wm + mf * 16 + g;
        #pragma unroll
        for (int nf = 0; nf < 4; nf++) {
            const int n = n0 + wn + nf * 8 + 2 * q;
            const float b0v = bias[n], b1v = bias[n + 1];
            const float o0 = acc[mf][nf][0] + b0v, o1 = acc[mf][nf][1] + b1v;
            const float o2 = acc[mf][nf][2] + b0v, o3 = acc[mf][nf][3] + b1v;
            if (MODE == 0) {
                __half* out = (__half*)outp;
                const int b_ = m >> 10, s_ = m & (SS - 1);
                const int h_ = n >> 6, e_ = n & 63;
                __half* base = out + ((size_t)(b_ * HH + h_) * SS + s_) * HDIM + e_;
                *(uint32_t*)base = f2h2(o0, o1);
                *(uint32_t*)(base + 8 * HDIM) = f2h2(o2, o3);
            } else {
                float* out = (float*)outp;
                *(float2*)(out + (size_t)m * DD + n) = make_float2(o0, o1);
                *(float2*)(out + (size_t)(m + 8) * DD + n) = make_float2(o2, o3);
            }
        }
    }
}

__global__ __launch_bounds__(256, 2)
void proj_kernel(const float* __restrict__ bq, const float* __restrict__ bk,
                 const float* __restrict__ bv)
{
    const __half *X, *Wt;
    const float* bias;
    __half* out;
    const int z = blockIdx.z;
    X = g_Xh + (size_t)z * (BB * SS * DD);
    Wt = g_Wt + (size_t)z * DD * DD;
    if (z == 0)      { bias = bq; out = g_Q; }
    else if (z == 1) { bias = bk; out = g_K; }
    else             { bias = bv; out = g_V; }
    gemm_f16_body<0>(X, Wt, bias, out);
}

__global__ __launch_bounds__(256, 2)
void outproj_kernel(const float* __restrict__ bo, float* __restrict__ out)
{
    gemm_f16_body<1>(g_attn, g_Wot, bo, out);
}

// ---------------------------------------------------------------------------
// fp16 mma flash attention (R12 structure; R13: log2-domain softmax with raw
// ex2.approx — folds the hidden FMUL inside every __expf into the score FFMA).
// Register-resident P, cp.async 3-slot KV ring, x4 ldmatrix fragments.
// Masking identical to reference: masked logits get the (scaled) NEG bias
// (kept in denominator), numerator zeroed by mask bit.
// ---------------------------------------------------------------------------
__global__ __launch_bounds__(256, 2)
void attn_kernel()
{
    extern __shared__ __half hsm[];

    const int bh = blockIdx.y;
    const int b_ = bh >> 4, h_ = bh & 15;
    const int q0 = blockIdx.x * 128;

    const __half* Qp = g_Q + (size_t)bh * SS * HDIM;
    const __half* Kp = g_K + (size_t)bh * SS * HDIM;
    const __half* Vp = g_V + (size_t)bh * SS * HDIM;

    const int tid = threadIdx.x, lane = tid & 31, w = tid >> 5;
    const int g = lane >> 2, q = lane & 3;
    const int l7 = lane & 7, lb3 = (lane >> 3) & 1, lb4 = lane >> 4;
    const int row0 = 16 * w + g;

    const uint32_t sbase = smem_u32(hsm);
    const int cRow = tid >> 3, cC8 = (tid & 7) * 8;
    auto cpaKV = [&](int t0, int slot) {
        const uint32_t kb = sbase + slot * 18432;
        #pragma unroll
        for (int i = 0; i < 2; i++) {
            const int row = cRow + i * 32;
            const uint32_t off = (uint32_t)(row * 144 + cC8 * 2);
            cpa16(kb + off,        Kp + (size_t)(t0 + row) * HDIM + cC8);
            cpa16(kb + 9216 + off, Vp + (size_t)(t0 + row) * HDIM + cC8);
        }
    };

    cpaKV(0, 0); CPA_COMMIT();

    __half* Qs = hsm + 9216;   // slot 1 region, 128x72 halves
    #pragma unroll
    for (int i = 0; i < 4; i++) {
        const int idx = tid + 256 * i;
        const int r = idx >> 3, c8 = (idx & 7) * 8;
        *(uint4*)&Qs[r * 72 + c8] = *(const uint4*)(Qp + (size_t)(q0 + r) * HDIM + c8);
    }
    __syncthreads();

    uint32_t qf[4][4];
    {
        const uint32_t qb = smem_u32(Qs);
        const int row = 16 * w + l7 + 8 * lb3;
        #pragma unroll
        for (int ks = 0; ks < 4; ks++)
            ldsm_x4(qf[ks], qb + (uint32_t)(row * 144 + (ks * 16 + 8 * lb4) * 2));
    }
    __syncthreads();   // Q hoist done; slot 1 may be overwritten

    float O[8][4];
    #pragma unroll
    for (int nf = 0; nf < 8; nf++)
        #pragma unroll
        for (int r = 0; r < 4; r++) O[nf][r] = 0.f;

    float mg = -1e30f, m8 = -1e30f, lg = 0.f, l8 = 0.f;

    const uint32_t* mrow  = g_mbits + ((size_t)b_ * SS + q0 + row0) * 32;
    const uint32_t* mrow8 = mrow + 8 * 32;

    const uint32_t klane = (uint32_t)((lb4 * 8 + l7) * 144 + lb3 * 16);
    const uint32_t vlane = (uint32_t)((lb3 * 8 + l7) * 144 + lb4 * 16);

    for (int t0 = 0; t0 < SS; t0 += 64) {
        const int t = t0 >> 6;
        const int slot = t % 3;
        if (t + 1 < 16) { cpaKV(t0 + 64, (t + 1) % 3); CPA_COMMIT(); CPA_WAIT1(); }
        else            { CPA_WAIT0(); }
        __syncthreads();

        const uint32_t kbase = sbase + slot * 18432;
        const uint32_t vbase = kbase + 9216;

        const int wc = t0 >> 5;
        const uint64_t M0 = ((uint64_t)mrow[wc]  | ((uint64_t)mrow[wc + 1]  << 32)) >> (2 * q);
        const uint64_t M8 = ((uint64_t)mrow8[wc] | ((uint64_t)mrow8[wc + 1] << 32)) >> (2 * q);

        // ---- QK^T ----
        float s[8][4];
        #pragma unroll
        for (int nf = 0; nf < 8; nf++)
            #pragma unroll
            for (int r = 0; r < 4; r++) s[nf][r] = 0.f;

        #pragma unroll
        for (int ks = 0; ks < 4; ks++) {
            #pragma unroll
            for (int nf2 = 0; nf2 < 4; nf2++) {
                uint32_t t4[4];
                ldsm_x4(t4, kbase + (uint32_t)(nf2 * 2304 + ks * 32) + klane);
                mma16(s[2 * nf2],     qf[ks], t4);
                mma16(s[2 * nf2 + 1], qf[ks], t4 + 2);
            }
        }

        // ---- log2-domain scale + mask bias, row max ----
        float rg = -1e30f, r8 = -1e30f;
        #pragma unroll
        for (int nf = 0; nf < 8; nf++) {
            const float fA0 = ((M0 >> (nf * 8)) & 1)     ? 0.f : NEGL;
            const float fB0 = ((M0 >> (nf * 8 + 1)) & 1) ? 0.f : NEGL;
            const float fA8 = ((M8 >> (nf * 8)) & 1)     ? 0.f : NEGL;
            const float fB8 = ((M8 >> (nf * 8 + 1)) & 1) ? 0.f : NEGL;
            s[nf][0] = s[nf][0] * SC_LOG2 + fA0;
            s[nf][1] = s[nf][1] * SC_LOG2 + fB0;
            s[nf][2] = s[nf][2] * SC_LOG2 + fA8;
            s[nf][3] = s[nf][3] * SC_LOG2 + fB8;
            rg = fmaxf(rg, fmaxf(s[nf][0], s[nf][1]));
            r8 = fmaxf(r8, fmaxf(s[nf][2], s[nf][3]));
        }
        rg = fmaxf(rg, __shfl_xor_sync(0xffffffffu, rg, 1));
        rg = fmaxf(rg, __shfl_xor_sync(0xffffffffu, rg, 2));
        r8 = fmaxf(r8, __shfl_xor_sync(0xffffffffu, r8, 1));
        r8 = fmaxf(r8, __shfl_xor_sync(0xffffffffu, r8, 2));

        const float mng = fmaxf(mg, rg), mn8 = fmaxf(m8, r8);
        const float ag = ex2(mg - mng), a8 = ex2(m8 - mn8);
        mg = mng; m8 = mn8;

        // ---- 2^x; denominator counts masked terms, numerator masked ----
        float sg = 0.f, s8sum = 0.f;
        #pragma unroll
        for (int nf = 0; nf < 8; nf++) {
            const float p0 = ex2(s[nf][0] - mg);
            const float p1 = ex2(s[nf][1] - mg);
            const float p2 = ex2(s[nf][2] - m8);
            const float p3 = ex2(s[nf][3] - m8);
            sg += p0 + p1; s8sum += p2 + p3;
            s[nf][0] = ((M0 >> (nf * 8)) & 1)     ? p0 : 0.f;
            s[nf][1] = ((M0 >> (nf * 8 + 1)) & 1) ? p1 : 0.f;
            s[nf][2] = ((M8 >> (nf * 8)) & 1)     ? p2 : 0.f;
            s[nf][3] = ((M8 >> (nf * 8 + 1)) & 1) ? p3 : 0.f;
            O[nf][0] *= ag; O[nf][1] *= ag;
            O[nf][2] *= a8; O[nf][3] *= a8;
        }
        sg    += __shfl_xor_sync(0xffffffffu, sg, 1);
        sg    += __shfl_xor_sync(0xffffffffu, sg, 2);
        s8sum += __shfl_xor_sync(0xffffffffu, s8sum, 1);
        s8sum += __shfl_xor_sync(0xffffffffu, s8sum, 2);
        lg = lg * ag + sg;
        l8 = l8 * a8 + s8sum;

        // ---- P @ V : P packed from registers (QK C-frag == PV A-frag) ----
        #pragma unroll
        for (int ks = 0; ks < 4; ks++) {
            uint32_t pf[4];
            pf[0] = f2h2(s[2 * ks][0],     s[2 * ks][1]);
            pf[1] = f2h2(s[2 * ks][2],     s[2 * ks][3]);
            pf[2] = f2h2(s[2 * ks + 1][0], s[2 * ks + 1][1]);
            pf[3] = f2h2(s[2 * ks + 1][2], s[2 * ks + 1][3]);
            #pragma unroll
            for (int nf2 = 0; nf2 < 4; nf2++) {
                uint32_t t4[4];
                ldsm_x4t(t4, vbase + (uint32_t)(ks * 2304 + nf2 * 32) + vlane);
                mma16(O[2 * nf2],     pf, t4);
                mma16(O[2 * nf2 + 1], pf, t4 + 2);
            }
        }
    }

    // ---- epilogue ----
    const float ig = 1.f / lg, i8 = 1.f / l8;
    __half* orow  = g_attn + (size_t)(b_ * SS + q0 + row0) * DD + h_ * HDIM;
    __half* orow8 = orow + 8 * DD;
    #pragma unroll
    for (int nf = 0; nf < 8; nf++) {
        const int e = nf * 8 + 2 * q;
        *(uint32_t*)(orow  + e) = f2h2(O[nf][0] * ig, O[nf][1] * ig);
        *(uint32_t*)(orow8 + e) = f2h2(O[nf][2] * i8, O[nf][3] * i8);
    }
}

// ---------------------------------------------------------------------------
extern "C" void kernel_launch(void* const* d_in, const int* in_sizes, int n_in,
                              void* d_out, int out_size)
{
    const float* q    = (const float*)d_in[0];
    const float* k    = (const float*)d_in[1];
    const float* v    = (const float*)d_in[2];
    const int*   mask = (const int*)  d_in[3];
    const float* Wq   = (const float*)d_in[4];
    const float* bq   = (const float*)d_in[5];
    const float* Wk   = (const float*)d_in[6];
    const float* bk   = (const float*)d_in[7];
    const float* Wv   = (const float*)d_in[8];
    const float* bv   = (const float*)d_in[9];
    const float* Wo   = (const float*)d_in[10];
    const float* bo   = (const float*)d_in[11];
    float* out = (float*)d_out;

    cudaFuncSetAttribute(proj_kernel,
                         cudaFuncAttributeMaxDynamicSharedMemorySize, 110592);
    cudaFuncSetAttribute(outproj_kernel,
                         cudaFuncAttributeMaxDynamicSharedMemorySize, 110592);
    cudaFuncSetAttribute(attn_kernel,
                         cudaFuncAttributeMaxDynamicSharedMemorySize, 55296);

    maskbits_kernel<<<BB * SS * (SS / 32) / 8, 256>>>(mask);

    x2h_kernel<<<dim3(BB * SS * DD / 2048, 1, 3), 256>>>(q, k, v);

    transpose_w<<<dim3(32, 32, 4), 256>>>(Wq, Wk, Wv, Wo);

    dim3 g1(8, 32, 3);                 // N/128, M/128, {Q,K,V}
    proj_kernel<<<g1, 256, 110592>>>(bq, bk, bv);

    dim3 g2(8, 64);                    // S/128 q-tiles, B*H
    attn_kernel<<<g2, 256, 55296>>>();

    dim3 g3(8, 32);                    // N/128, M/128
    outproj_kernel<<<g3, 256, 110592>>>(bo, out);
}

// round 15
// speedup vs baseline: 6.6505x; 1.0847x over previous
#include <cuda_runtime.h>
#include <cuda_fp16.h>
#include <math.h>
#include <stdint.h>

#define BB 4
#define SS 1024
#define DD 1024
#define HH 16
#define HDIM 64

// log2-domain softmax constants: p = 2^(dot*SC + NEGL - m)  ==  exp(dot*scale + NEG - m)
#define SC_LOG2  0.04508422003f      // (1/32) * log2(e)
#define NEGL     -1.44269504e10f     // -1e10  * log2(e)

// Scratch (module-load allocated; no runtime allocs)
__device__ __half g_Xh[3*BB*SS*DD];           // Xq/Xk/Xv pre-converted to fp16
__device__ __half g_Q[BB*HH*SS*HDIM];
__device__ __half g_K[BB*HH*SS*HDIM];
__device__ __half g_V[BB*HH*SS*HDIM];
__device__ __half g_attn[BB*SS*DD];
__device__ uint32_t g_mbits[BB*SS*(SS/32)];   // packed mask bits
__device__ __half g_Wt[3*DD*DD];              // Wq/Wk/Wv transposed to [n][k], fp16
__device__ __half g_Wot[DD*DD];               // Wo transposed to [n][k], fp16

// ---------------------------------------------------------------------------
// helpers
// ---------------------------------------------------------------------------
__device__ __forceinline__ uint32_t f2h2(float lo, float hi) {
    __half2 h = __floats2half2_rn(lo, hi);
    return *reinterpret_cast<uint32_t*>(&h);
}

__device__ __forceinline__ float ex2(float x) {
    float y;
    asm("ex2.approx.f32 %0, %1;" : "=f"(y) : "f"(x));
    return y;
}

__device__ __forceinline__ uint32_t h2ex2(uint32_t x) {
    uint32_t y;
    asm("ex2.approx.f16x2 %0, %1;" : "=r"(y) : "r"(x));
    return y;
}

__device__ __forceinline__ void mma16(float* c, const uint32_t* a, const uint32_t* b) {
    asm volatile(
        "mma.sync.aligned.m16n8k16.row.col.f32.f16.f16.f32 "
        "{%0,%1,%2,%3}, {%4,%5,%6,%7}, {%8,%9}, {%0,%1,%2,%3};"
        : "+f"(c[0]), "+f"(c[1]), "+f"(c[2]), "+f"(c[3])
        : "r"(a[0]), "r"(a[1]), "r"(a[2]), "r"(a[3]), "r"(b[0]), "r"(b[1]));
}

__device__ __forceinline__ uint32_t smem_u32(const void* p) {
    uint32_t a;
    asm("{ .reg .u64 t; cvta.to.shared.u64 t, %1; cvt.u32.u64 %0, t; }"
        : "=r"(a) : "l"(p));
    return a;
}

__device__ __forceinline__ void ldsm_x4(uint32_t* r, uint32_t a) {
    asm volatile("ldmatrix.sync.aligned.m8n8.x4.shared.b16 {%0,%1,%2,%3}, [%4];"
        : "=r"(r[0]), "=r"(r[1]), "=r"(r[2]), "=r"(r[3]) : "r"(a));
}
__device__ __forceinline__ void ldsm_x4t(uint32_t* r, uint32_t a) {
    asm volatile("ldmatrix.sync.aligned.m8n8.x4.trans.shared.b16 {%0,%1,%2,%3}, [%4];"
        : "=r"(r[0]), "=r"(r[1]), "=r"(r[2]), "=r"(r[3]) : "r"(a));
}

__device__ __forceinline__ void cpa16(uint32_t dst, const void* src) {
    asm volatile("cp.async.cg.shared.global [%0], [%1], 16;" :: "r"(dst), "l"(src));
}
#define CPA_COMMIT() asm volatile("cp.async.commit_group;")
#define CPA_WAIT0()  asm volatile("cp.async.wait_group 0;")
#define CPA_WAIT1()  asm volatile("cp.async.wait_group 1;")

// ---------------------------------------------------------------------------
// Merged prepass: flat-grid dispatch over three jobs
//   [0, 16384)        maskbits  (pack mask ints to bits via ballot)
//   [16384, 22528)    x2h       (X fp32 -> fp16, z = 0..2)
//   [22528, 26624)    transpose (W -> [n][k] fp16, z = 0..3)
// ---------------------------------------------------------------------------
__global__ __launch_bounds__(256)
void prepass_kernel(const int* __restrict__ mask,
                    const float* __restrict__ Xq, const float* __restrict__ Xk,
                    const float* __restrict__ Xv,
                    const float* __restrict__ Wq, const float* __restrict__ Wk,
                    const float* __restrict__ Wv, const float* __restrict__ Wo)
{
    __shared__ float t[32][33];
    const int bid = blockIdx.x;
    const int tid = threadIdx.x;

    if (bid < 16384) {
        const int widx = bid * 8 + (tid >> 5);
        const int lanev = mask[(size_t)widx * 32 + (tid & 31)];
        const uint32_t bal = __ballot_sync(0xffffffffu, lanev != 0);
        if ((tid & 31) == 0) g_mbits[widx] = bal;
        return;
    }
    if (bid < 22528) {
        const int r = bid - 16384;
        const int z = r >> 11, blk = r & 2047;
        const float* src = (z == 0) ? Xq : (z == 1) ? Xk : Xv;
        __half* dst = g_Xh + (size_t)z * (BB * SS * DD);
        const size_t i8 = ((size_t)blk * 256 + tid) * 8;
        float4 a = *(const float4*)(src + i8);
        float4 b = *(const float4*)(src + i8 + 4);
        uint4 o;
        o.x = f2h2(a.x, a.y); o.y = f2h2(a.z, a.w);
        o.z = f2h2(b.x, b.y); o.w = f2h2(b.z, b.w);
        *(uint4*)(dst + i8) = o;
        return;
    }
    {
        const int r = bid - 22528;
        const int z = r >> 10, rem = r & 1023;
        const int n0 = (rem & 31) * 32, k0 = (rem >> 5) * 32;
        const float* W = (z == 0) ? Wq : (z == 1) ? Wk : (z == 2) ? Wv : Wo;
        __half* out = (z < 3) ? (g_Wt + (size_t)z * DD * DD) : g_Wot;
        const int tx = tid & 31, ty = tid >> 5;

        #pragma unroll
        for (int j = 0; j < 4; j++) {
            const int k = k0 + ty + 8 * j;
            const int n = n0 + tx;
            const float v = (z < 3)
                ? W[(size_t)(n >> 6) * (DD * HDIM) + (size_t)k * HDIM + (n & 63)]
                : W[(size_t)k * DD + n];
            t[ty + 8 * j][tx] = v;
        }
        __syncthreads();
        #pragma unroll
        for (int j = 0; j < 4; j++) {
            const int n = n0 + ty + 8 * j;
            const int k = k0 + tx;
            out[(size_t)n * DD + k] = __float2half_rn(t[tx][ty + 8 * j]);
        }
    }
}

// ---------------------------------------------------------------------------
// fp16 GEMM (unchanged from R13): BK=64, 3-slot cp.async ring, wait_group 1.
// dyn smem: 3 slots x (A[128][72] + B[128][72]) = 110592 B (2 CTAs/SM).
// ---------------------------------------------------------------------------
template<int MODE>
__device__ __forceinline__ void gemm_f16_body(const __half* __restrict__ X,
                                              const __half* __restrict__ Wt,
                                              const float* __restrict__ bias,
                                              void* __restrict__ outp)
{
    extern __shared__ __half hsm[];
    const int tid = threadIdx.x, lane = tid & 31, w = tid >> 5;
    const int g = lane >> 2, q = lane & 3;
    const int l7 = lane & 7, lb3 = (lane >> 3) & 1, lb4 = lane >> 4;
    const int wm = (w >> 2) * 64, wn = (w & 3) * 32;
    const int m0 = blockIdx.y * 128, n0 = blockIdx.x * 128;
    const uint32_t sbase = smem_u32(hsm);

    float acc[4][4][4];
    #pragma unroll
    for (int i = 0; i < 4; i++)
        #pragma unroll
        for (int j = 0; j < 4; j++)
            #pragma unroll
            for (int r = 0; r < 4; r++) acc[i][j][r] = 0.f;

    auto ldg_async = [&](int kt, int slot) {
        const int kb = kt * 64;
        const uint32_t abase = sbase + slot * 36864;
        #pragma unroll
        for (int i = 0; i < 4; i++) {
            const int idx = tid + 256 * i;
            const int row = idx >> 3, c8 = (idx & 7) * 8;
            const uint32_t off = (uint32_t)(row * 144 + c8 * 2);
            cpa16(abase + off,         X  + (size_t)(m0 + row) * DD + kb + c8);
            cpa16(abase + 18432 + off, Wt + (size_t)(n0 + row) * DD + kb + c8);
        }
    };

    auto compute = [&](int slot) {
        const uint32_t Abase = sbase + slot * 36864;
        const uint32_t Bbase = Abase + 18432;
        #pragma unroll
        for (int ks = 0; ks < 4; ks++) {
            uint32_t af[4][4], bf[4][2];
            #pragma unroll
            for (int mf = 0; mf < 4; mf++) {
                const int row = wm + mf * 16 + l7 + 8 * lb3;
                ldsm_x4(af[mf], Abase + (uint32_t)(row * 144 + (ks * 16 + 8 * lb4) * 2));
            }
            #pragma unroll
            for (int nfp = 0; nfp < 2; nfp++) {
                uint32_t t4[4];
                const int row = wn + nfp * 16 + 8 * lb4 + l7;
                ldsm_x4(t4, Bbase + (uint32_t)(row * 144 + (ks * 16 + 8 * lb3) * 2));
                bf[2 * nfp][0] = t4[0]; bf[2 * nfp][1] = t4[1];
                bf[2 * nfp + 1][0] = t4[2]; bf[2 * nfp + 1][1] = t4[3];
            }
            #pragma unroll
            for (int mf = 0; mf < 4; mf++)
                #pragma unroll
                for (int nf = 0; nf < 4; nf++)
                    mma16(acc[mf][nf], af[mf], bf[nf]);
        }
    };

    ldg_async(0, 0); CPA_COMMIT();

    for (int kt = 0; kt < 16; kt++) {
        const int slot = kt % 3;
        if (kt < 15) { ldg_async(kt + 1, (kt + 1) % 3); CPA_COMMIT(); CPA_WAIT1(); }
        else         { CPA_WAIT0(); }
        __syncthreads();
        compute(slot);
    }

    #pragma unroll
    for (int mf = 0; mf < 4; mf++) {
        const int m = m0 + wm + mf * 16 + g;
        #pragma unroll
        for (int nf = 0; nf < 4; nf++) {
            const int n = n0 + wn + nf * 8 + 2 * q;
            const float b0v = bias[n], b1v = bias[n + 1];
            const float o0 = acc[mf][nf][0] + b0v, o1 = acc[mf][nf][1] + b1v;
            const float o2 = acc[mf][nf][2] + b0v, o3 = acc[mf][nf][3] + b1v;
            if (MODE == 0) {
                __half* out = (__half*)outp;
                const int b_ = m >> 10, s_ = m & (SS - 1);
                const int h_ = n >> 6, e_ = n & 63;
                __half* base = out + ((size_t)(b_ * HH + h_) * SS + s_) * HDIM + e_;
                *(uint32_t*)base = f2h2(o0, o1);
                *(uint32_t*)(base + 8 * HDIM) = f2h2(o2, o3);
            } else {
                float* out = (float*)outp;
                *(float2*)(out + (size_t)m * DD + n) = make_float2(o0, o1);
                *(float2*)(out + (size_t)(m + 8) * DD + n) = make_float2(o2, o3);
            }
        }
    }
}

__global__ __launch_bounds__(256, 2)
void proj_kernel(const float* __restrict__ bq, const float* __restrict__ bk,
                 const float* __restrict__ bv)
{
    const __half *X, *Wt;
    const float* bias;
    __half* out;
    const int z = blockIdx.z;
    X = g_Xh + (size_t)z * (BB * SS * DD);
    Wt = g_Wt + (size_t)z * DD * DD;
    if (z == 0)      { bias = bq; out = g_Q; }
    else if (z == 1) { bias = bk; out = g_K; }
    else             { bias = bv; out = g_V; }
    gemm_f16_body<0>(X, Wt, bias, out);
}

__global__ __launch_bounds__(256, 2)
void outproj_kernel(const float* __restrict__ bo, float* __restrict__ out)
{
    gemm_f16_body<1>(g_attn, g_Wot, bo, out);
}

// ---------------------------------------------------------------------------
// fp16 mma flash attention.
// R14: (a) KV tiles of 128 keys (two 64-key halves through the same softmax)
//      -> 8 barriers instead of 16; (b) f16x2 ex2 softmax: pack (s-m) pairs
//      (f2h2 we already paid for), ONE ex2.approx.f16x2 per pair (MUFU
//      halved); denominator summed in fp32 via half2->float2; numerator
//      masking = packed AND. Masked logits saturate to -inf in fp16 ->
//      ex2 = 0, same as the fp32 flush. All-masked row: diff 0 -> 1. Exactly
//      reference semantics (masked terms counted in denominator, numerator
//      zeroed).
// dyn smem: 3 slots x (K[128][72] + V[128][72]) = 110592 B.
// ---------------------------------------------------------------------------
__global__ __launch_bounds__(256, 2)
void attn_kernel()
{
    extern __shared__ __half hsm[];

    const int bh = blockIdx.y;
    const int b_ = bh >> 4, h_ = bh & 15;
    const int q0 = blockIdx.x * 128;

    const __half* Qp = g_Q + (size_t)bh * SS * HDIM;
    const __half* Kp = g_K + (size_t)bh * SS * HDIM;
    const __half* Vp = g_V + (size_t)bh * SS * HDIM;

    const int tid = threadIdx.x, lane = tid & 31, w = tid >> 5;
    const int g = lane >> 2, q = lane & 3;
    const int l7 = lane & 7, lb3 = (lane >> 3) & 1, lb4 = lane >> 4;
    const int row0 = 16 * w + g;

    const uint32_t sbase = smem_u32(hsm);
    // per-thread cp.async mapping for a 128x64 tile (1024 chunks of 8 halves)
    auto cpaKV = [&](int t0, int slot) {
        const uint32_t kb = sbase + slot * 36864;
        #pragma unroll
        for (int i = 0; i < 4; i++) {
            const int idx = tid + 256 * i;
            const int row = idx >> 3, c8 = (idx & 7) * 8;
            const uint32_t off = (uint32_t)(row * 144 + c8 * 2);
            cpa16(kb + off,         Kp + (size_t)(t0 + row) * HDIM + c8);
            cpa16(kb + 18432 + off, Vp + (size_t)(t0 + row) * HDIM + c8);
        }
    };

    cpaKV(0, 0); CPA_COMMIT();

    // Q staged in slot 1's K region (bytes [36864, 55296)) — disjoint from
    // the in-flight slot 0 load; consumed before slot 1 is first written.
    __half* Qs = hsm + 18432;
    #pragma unroll
    for (int i = 0; i < 4; i++) {
        const int idx = tid + 256 * i;
        const int r = idx >> 3, c8 = (idx & 7) * 8;
        *(uint4*)&Qs[r * 72 + c8] = *(const uint4*)(Qp + (size_t)(q0 + r) * HDIM + c8);
    }
    __syncthreads();

    uint32_t qf[4][4];
    {
        const uint32_t qb = sbase + 36864;
        const int row = 16 * w + l7 + 8 * lb3;
        #pragma unroll
        for (int ks = 0; ks < 4; ks++)
            ldsm_x4(qf[ks], qb + (uint32_t)(row * 144 + (ks * 16 + 8 * lb4) * 2));
    }
    __syncthreads();   // Q hoist done; slot 1 may be overwritten

    float O[8][4];
    #pragma unroll
    for (int nf = 0; nf < 8; nf++)
        #pragma unroll
        for (int r = 0; r < 4; r++) O[nf][r] = 0.f;

    float mg = -1e30f, m8 = -1e30f, lg = 0.f, l8 = 0.f;

    const uint32_t* mrow  = g_mbits + ((size_t)b_ * SS + q0 + row0) * 32;
    const uint32_t* mrow8 = mrow + 8 * 32;

    const uint32_t klane = (uint32_t)((lb4 * 8 + l7) * 144 + lb3 * 16);
    const uint32_t vlane = (uint32_t)((lb3 * 8 + l7) * 144 + lb4 * 16);

    for (int t = 0; t < 8; t++) {
        const int slot = t % 3;
        if (t + 1 < 8) { cpaKV((t + 1) * 128, (t + 1) % 3); CPA_COMMIT(); CPA_WAIT1(); }
        else           { CPA_WAIT0(); }
        __syncthreads();

        const uint32_t kslot = sbase + slot * 36864;

        #pragma unroll
        for (int h = 0; h < 2; h++) {
            const uint32_t kbase = kslot + h * 9216;
            const uint32_t vbase = kslot + 18432 + h * 9216;

            const int wc = t * 4 + 2 * h;
            const uint64_t M0 = ((uint64_t)mrow[wc]  | ((uint64_t)mrow[wc + 1]  << 32)) >> (2 * q);
            const uint64_t M8 = ((uint64_t)mrow8[wc] | ((uint64_t)mrow8[wc + 1] << 32)) >> (2 * q);

            // ---- QK^T ----
            float s[8][4];
            #pragma unroll
            for (int nf = 0; nf < 8; nf++)
                #pragma unroll
                for (int r = 0; r < 4; r++) s[nf][r] = 0.f;

            #pragma unroll
            for (int ks = 0; ks < 4; ks++) {
                #pragma unroll
                for (int nf2 = 0; nf2 < 4; nf2++) {
                    uint32_t t4[4];
                    ldsm_x4(t4, kbase + (uint32_t)(nf2 * 2304 + ks * 32) + klane);
                    mma16(s[2 * nf2],     qf[ks], t4);
                    mma16(s[2 * nf2 + 1], qf[ks], t4 + 2);
                }
            }

            // ---- log2-domain scale + mask bias, row max ----
            float rg = -1e30f, r8 = -1e30f;
            #pragma unroll
            for (int nf = 0; nf < 8; nf++) {
                const float fA0 = ((M0 >> (nf * 8)) & 1)     ? 0.f : NEGL;
                const float fB0 = ((M0 >> (nf * 8 + 1)) & 1) ? 0.f : NEGL;
                const float fA8 = ((M8 >> (nf * 8)) & 1)     ? 0.f : NEGL;
                const float fB8 = ((M8 >> (nf * 8 + 1)) & 1) ? 0.f : NEGL;
                s[nf][0] = s[nf][0] * SC_LOG2 + fA0;
                s[nf][1] = s[nf][1] * SC_LOG2 + fB0;
                s[nf][2] = s[nf][2] * SC_LOG2 + fA8;
                s[nf][3] = s[nf][3] * SC_LOG2 + fB8;
                rg = fmaxf(rg, fmaxf(s[nf][0], s[nf][1]));
                r8 = fmaxf(r8, fmaxf(s[nf][2], s[nf][3]));
            }
            rg = fmaxf(rg, __shfl_xor_sync(0xffffffffu, rg, 1));
            rg = fmaxf(rg, __shfl_xor_sync(0xffffffffu, rg, 2));
            r8 = fmaxf(r8, __shfl_xor_sync(0xffffffffu, r8, 1));
            r8 = fmaxf(r8, __shfl_xor_sync(0xffffffffu, r8, 2));

            const float mng = fmaxf(mg, rg), mn8 = fmaxf(m8, r8);
            const float ag = ex2(mg - mng), a8 = ex2(m8 - mn8);
            mg = mng; m8 = mn8;

            // ---- f16x2 ex2: denominator (fp32 sum) + packed masked P ----
            uint32_t P01[8], P23[8];
            float sg = 0.f, s8sum = 0.f;
            #pragma unroll
            for (int nf = 0; nf < 8; nf++) {
                const uint32_t e01 = h2ex2(f2h2(s[nf][0] - mg, s[nf][1] - mg));
                const uint32_t e23 = h2ex2(f2h2(s[nf][2] - m8, s[nf][3] - m8));
                const float2 f01 = __half22float2(*reinterpret_cast<const __half2*>(&e01));
                const float2 f23 = __half22float2(*reinterpret_cast<const __half2*>(&e23));
                sg    += f01.x + f01.y;
                s8sum += f23.x + f23.y;
                const uint32_t b0 = (uint32_t)(M0 >> (nf * 8));
                const uint32_t b8 = (uint32_t)(M8 >> (nf * 8));
                const uint32_t msk01 = ((b0 & 1) ? 0x0000FFFFu : 0u) | ((b0 & 2) ? 0xFFFF0000u : 0u);
                const uint32_t msk23 = ((b8 & 1) ? 0x0000FFFFu : 0u) | ((b8 & 2) ? 0xFFFF0000u : 0u);
                P01[nf] = e01 & msk01;
                P23[nf] = e23 & msk23;
                O[nf][0] *= ag; O[nf][1] *= ag;
                O[nf][2] *= a8; O[nf][3] *= a8;
            }
            sg    += __shfl_xor_sync(0xffffffffu, sg, 1);
            sg    += __shfl_xor_sync(0xffffffffu, sg, 2);
            s8sum += __shfl_xor_sync(0xffffffffu, s8sum, 1);
            s8sum += __shfl_xor_sync(0xffffffffu, s8sum, 2);
            lg = lg * ag + sg;
            l8 = l8 * a8 + s8sum;

            // ---- P @ V : P already packed (QK C-frag == PV A-frag) ----
            #pragma unroll
            for (int ks = 0; ks < 4; ks++) {
                uint32_t pf[4] = { P01[2 * ks], P23[2 * ks],
                                   P01[2 * ks + 1], P23[2 * ks + 1] };
                #pragma unroll
                for (int nf2 = 0; nf2 < 4; nf2++) {
                    uint32_t t4[4];
                    ldsm_x4t(t4, vbase + (uint32_t)(ks * 2304 + nf2 * 32) + vlane);
                    mma16(O[2 * nf2],     pf, t4);
                    mma16(O[2 * nf2 + 1], pf, t4 + 2);
                }
            }
        }
    }

    // ---- epilogue ----
    const float ig = 1.f / lg, i8 = 1.f / l8;
    __half* orow  = g_attn + (size_t)(b_ * SS + q0 + row0) * DD + h_ * HDIM;
    __half* orow8 = orow + 8 * DD;
    #pragma unroll
    for (int nf = 0; nf < 8; nf++) {
        const int e = nf * 8 + 2 * q;
        *(uint32_t*)(orow  + e) = f2h2(O[nf][0] * ig, O[nf][1] * ig);
        *(uint32_t*)(orow8 + e) = f2h2(O[nf][2] * i8, O[nf][3] * i8);
    }
}

// ---------------------------------------------------------------------------
extern "C" void kernel_launch(void* const* d_in, const int* in_sizes, int n_in,
                              void* d_out, int out_size)
{
    const float* q    = (const float*)d_in[0];
    const float* k    = (const float*)d_in[1];
    const float* v    = (const float*)d_in[2];
    const int*   mask = (const int*)  d_in[3];
    const float* Wq   = (const float*)d_in[4];
    const float* bq   = (const float*)d_in[5];
    const float* Wk   = (const float*)d_in[6];
    const float* bk   = (const float*)d_in[7];
    const float* Wv   = (const float*)d_in[8];
    const float* bv   = (const float*)d_in[9];
    const float* Wo   = (const float*)d_in[10];
    const float* bo   = (const float*)d_in[11];
    float* out = (float*)d_out;

    cudaFuncSetAttribute(proj_kernel,
                         cudaFuncAttributeMaxDynamicSharedMemorySize, 110592);
    cudaFuncSetAttribute(outproj_kernel,
                         cudaFuncAttributeMaxDynamicSharedMemorySize, 110592);
    cudaFuncSetAttribute(attn_kernel,
                         cudaFuncAttributeMaxDynamicSharedMemorySize, 110592);

    prepass_kernel<<<26624, 256>>>(mask, q, k, v, Wq, Wk, Wv, Wo);

    dim3 g1(8, 32, 3);                 // N/128, M/128, {Q,K,V}
    proj_kernel<<<g1, 256, 110592>>>(bq, bk, bv);

    dim3 g2(8, 64);                    // S/128 q-tiles, B*H
    attn_kernel<<<g2, 256, 110592>>>();

    dim3 g3(8, 32);                    // N/128, M/128
    outproj_kernel<<<g3, 256, 110592>>>(bo, out);
}

// round 17
// speedup vs baseline: 6.7078x; 1.0086x over previous
#include <cuda_runtime.h>
#include <cuda_fp16.h>
#include <math.h>
#include <stdint.h>

#define BB 4
#define SS 1024
#define DD 1024
#define HH 16
#define HDIM 64

// log2-domain softmax: p = 2^(dot*SC - m).  Mask applied as packed f16 -inf
// bias before ex2 (exact: in fp32 the reference's exp(s + NEG - max) == 0).
#define SC_LOG2  0.04508422003f      // (1/32) * log2(e)

// Scratch (module-load allocated; no runtime allocs)
__device__ __half g_Xh[3*BB*SS*DD];           // Xq/Xk/Xv pre-converted to fp16
__device__ __half g_Q[BB*HH*SS*HDIM];
__device__ __half g_K[BB*HH*SS*HDIM];
__device__ __half g_V[BB*HH*SS*HDIM];
__device__ __half g_attn[BB*SS*DD];
__device__ uint32_t g_mbits[BB*SS*(SS/32)];   // packed mask bits
__device__ __half g_Wt[3*DD*DD];              // Wq/Wk/Wv transposed to [n][k], fp16
__device__ __half g_Wot[DD*DD];               // Wo transposed to [n][k], fp16

// ---------------------------------------------------------------------------
// helpers
// ---------------------------------------------------------------------------
__device__ __forceinline__ uint32_t f2h2(float lo, float hi) {
    __half2 h = __floats2half2_rn(lo, hi);
    return *reinterpret_cast<uint32_t*>(&h);
}

__device__ __forceinline__ float ex2(float x) {
    float y;
    asm("ex2.approx.f32 %0, %1;" : "=f"(y) : "f"(x));
    return y;
}

__device__ __forceinline__ uint32_t h2ex2(uint32_t x) {
    uint32_t y;
    asm("ex2.approx.f16x2 %0, %1;" : "=r"(y) : "r"(x));
    return y;
}

__device__ __forceinline__ uint32_t h2add(uint32_t a, uint32_t b) {
    __half2 r = __hadd2(*reinterpret_cast<const __half2*>(&a),
                        *reinterpret_cast<const __half2*>(&b));
    return *reinterpret_cast<uint32_t*>(&r);
}

__device__ __forceinline__ uint32_t h2max(uint32_t a, uint32_t b) {
    __half2 r = __hmax2(*reinterpret_cast<const __half2*>(&a),
                        *reinterpret_cast<const __half2*>(&b));
    return *reinterpret_cast<uint32_t*>(&r);
}

__device__ __forceinline__ void mma16(float* c, const uint32_t* a, const uint32_t* b) {
    asm volatile(
        "mma.sync.aligned.m16n8k16.row.col.f32.f16.f16.f32 "
        "{%0,%1,%2,%3}, {%4,%5,%6,%7}, {%8,%9}, {%0,%1,%2,%3};"
        : "+f"(c[0]), "+f"(c[1]), "+f"(c[2]), "+f"(c[3])
        : "r"(a[0]), "r"(a[1]), "r"(a[2]), "r"(a[3]), "r"(b[0]), "r"(b[1]));
}

__device__ __forceinline__ uint32_t smem_u32(const void* p) {
    uint32_t a;
    asm("{ .reg .u64 t; cvta.to.shared.u64 t, %1; cvt.u32.u64 %0, t; }"
        : "=r"(a) : "l"(p));
    return a;
}

__device__ __forceinline__ void ldsm_x4(uint32_t* r, uint32_t a) {
    asm volatile("ldmatrix.sync.aligned.m8n8.x4.shared.b16 {%0,%1,%2,%3}, [%4];"
        : "=r"(r[0]), "=r"(r[1]), "=r"(r[2]), "=r"(r[3]) : "r"(a));
}
__device__ __forceinline__ void ldsm_x4t(uint32_t* r, uint32_t a) {
    asm volatile("ldmatrix.sync.aligned.m8n8.x4.trans.shared.b16 {%0,%1,%2,%3}, [%4];"
        : "=r"(r[0]), "=r"(r[1]), "=r"(r[2]), "=r"(r[3]) : "r"(a));
}

__device__ __forceinline__ void cpa16(uint32_t dst, const void* src) {
    asm volatile("cp.async.cg.shared.global [%0], [%1], 16;" :: "r"(dst), "l"(src));
}
#define CPA_COMMIT() asm volatile("cp.async.commit_group;")
#define CPA_WAIT0()  asm volatile("cp.async.wait_group 0;")
#define CPA_WAIT1()  asm volatile("cp.async.wait_group 1;")

// ---------------------------------------------------------------------------
// Merged prepass: flat-grid dispatch over three jobs
//   [0, 16384)        maskbits  (pack mask ints to bits via ballot)
//   [16384, 22528)    x2h       (X fp32 -> fp16, z = 0..2)
//   [22528, 26624)    transpose (W -> [n][k] fp16, z = 0..3)
// ---------------------------------------------------------------------------
__global__ __launch_bounds__(256)
void prepass_kernel(const int* __restrict__ mask,
                    const float* __restrict__ Xq, const float* __restrict__ Xk,
                    const float* __restrict__ Xv,
                    const float* __restrict__ Wq, const float* __restrict__ Wk,
                    const float* __restrict__ Wv, const float* __restrict__ Wo)
{
    __shared__ float t[32][33];
    const int bid = blockIdx.x;
    const int tid = threadIdx.x;

    if (bid < 16384) {
        const int widx = bid * 8 + (tid >> 5);
        const int lanev = mask[(size_t)widx * 32 + (tid & 31)];
        const uint32_t bal = __ballot_sync(0xffffffffu, lanev != 0);
        if ((tid & 31) == 0) g_mbits[widx] = bal;
        return;
    }
    if (bid < 22528) {
        const int r = bid - 16384;
        const int z = r >> 11, blk = r & 2047;
        const float* src = (z == 0) ? Xq : (z == 1) ? Xk : Xv;
        __half* dst = g_Xh + (size_t)z * (BB * SS * DD);
        const size_t i8 = ((size_t)blk * 256 + tid) * 8;
        float4 a = *(const float4*)(src + i8);
        float4 b = *(const float4*)(src + i8 + 4);
        uint4 o;
        o.x = f2h2(a.x, a.y); o.y = f2h2(a.z, a.w);
        o.z = f2h2(b.x, b.y); o.w = f2h2(b.z, b.w);
        *(uint4*)(dst + i8) = o;
        return;
    }
    {
        const int r = bid - 22528;
        const int z = r >> 10, rem = r & 1023;
        const int n0 = (rem & 31) * 32, k0 = (rem >> 5) * 32;
        const float* W = (z == 0) ? Wq : (z == 1) ? Wk : (z == 2) ? Wv : Wo;
        __half* out = (z < 3) ? (g_Wt + (size_t)z * DD * DD) : g_Wot;
        const int tx = tid & 31, ty = tid >> 5;

        #pragma unroll
        for (int j = 0; j < 4; j++) {
            const int k = k0 + ty + 8 * j;
            const int n = n0 + tx;
            const float v = (z < 3)
                ? W[(size_t)(n >> 6) * (DD * HDIM) + (size_t)k * HDIM + (n & 63)]
                : W[(size_t)k * DD + n];
            t[ty + 8 * j][tx] = v;
        }
        __syncthreads();
        #pragma unroll
        for (int j = 0; j < 4; j++) {
            const int n = n0 + ty + 8 * j;
            const int k = k0 + tx;
            out[(size_t)n * DD + k] = __float2half_rn(t[tx][ty + 8 * j]);
        }
    }
}

// ---------------------------------------------------------------------------
// fp16 GEMM (unchanged from R13): BK=64, 3-slot cp.async ring, wait_group 1.
// dyn smem: 3 slots x (A[128][72] + B[128][72]) = 110592 B (2 CTAs/SM).
// ---------------------------------------------------------------------------
template<int MODE>
__device__ __forceinline__ void gemm_f16_body(const __half* __restrict__ X,
                                              const __half* __restrict__ Wt,
                                              const float* __restrict__ bias,
                                              void* __restrict__ outp)
{
    extern __shared__ __half hsm[];
    const int tid = threadIdx.x, lane = tid & 31, w = tid >> 5;
    const int g = lane >> 2, q = lane & 3;
    const int l7 = lane & 7, lb3 = (lane >> 3) & 1, lb4 = lane >> 4;
    const int wm = (w >> 2) * 64, wn = (w & 3) * 32;
    const int m0 = blockIdx.y * 128, n0 = blockIdx.x * 128;
    const uint32_t sbase = smem_u32(hsm);

    float acc[4][4][4];
    #pragma unroll
    for (int i = 0; i < 4; i++)
        #pragma unroll
        for (int j = 0; j < 4; j++)
            #pragma unroll
            for (int r = 0; r < 4; r++) acc[i][j][r] = 0.f;

    auto ldg_async = [&](int kt, int slot) {
        const int kb = kt * 64;
        const uint32_t abase = sbase + slot * 36864;
        #pragma unroll
        for (int i = 0; i < 4; i++) {
            const int idx = tid + 256 * i;
            const int row = idx >> 3, c8 = (idx & 7) * 8;
            const uint32_t off = (uint32_t)(row * 144 + c8 * 2);
            cpa16(abase + off,         X  + (size_t)(m0 + row) * DD + kb + c8);
            cpa16(abase + 18432 + off, Wt + (size_t)(n0 + row) * DD + kb + c8);
        }
    };

    auto compute = [&](int slot) {
        const uint32_t Abase = sbase + slot * 36864;
        const uint32_t Bbase = Abase + 18432;
        #pragma unroll
        for (int ks = 0; ks < 4; ks++) {
            uint32_t af[4][4], bf[4][2];
            #pragma unroll
            for (int mf = 0; mf < 4; mf++) {
                const int row = wm + mf * 16 + l7 + 8 * lb3;
                ldsm_x4(af[mf], Abase + (uint32_t)(row * 144 + (ks * 16 + 8 * lb4) * 2));
            }
            #pragma unroll
            for (int nfp = 0; nfp < 2; nfp++) {
                uint32_t t4[4];
                const int row = wn + nfp * 16 + 8 * lb4 + l7;
                ldsm_x4(t4, Bbase + (uint32_t)(row * 144 + (ks * 16 + 8 * lb3) * 2));
                bf[2 * nfp][0] = t4[0]; bf[2 * nfp][1] = t4[1];
                bf[2 * nfp + 1][0] = t4[2]; bf[2 * nfp + 1][1] = t4[3];
            }
            #pragma unroll
            for (int mf = 0; mf < 4; mf++)
                #pragma unroll
                for (int nf = 0; nf < 4; nf++)
                    mma16(acc[mf][nf], af[mf], bf[nf]);
        }
    };

    ldg_async(0, 0); CPA_COMMIT();

    for (int kt = 0; kt < 16; kt++) {
        const int slot = kt % 3;
        if (kt < 15) { ldg_async(kt + 1, (kt + 1) % 3); CPA_COMMIT(); CPA_WAIT1(); }
        else         { CPA_WAIT0(); }
        __syncthreads();
        compute(slot);
    }

    #pragma unroll
    for (int mf = 0; mf < 4; mf++) {
        const int m = m0 + wm + mf * 16 + g;
        #pragma unroll
        for (int nf = 0; nf < 4; nf++) {
            const int n = n0 + wn + nf * 8 + 2 * q;
            const float b0v = bias[n], b1v = bias[n + 1];
            const float o0 = acc[mf][nf][0] + b0v, o1 = acc[mf][nf][1] + b1v;
            const float o2 = acc[mf][nf][2] + b0v, o3 = acc[mf][nf][3] + b1v;
            if (MODE == 0) {
                __half* out = (__half*)outp;
                const int b_ = m >> 10, s_ = m & (SS - 1);
                const int h_ = n >> 6, e_ = n & 63;
                __half* base = out + ((size_t)(b_ * HH + h_) * SS + s_) * HDIM + e_;
                *(uint32_t*)base = f2h2(o0, o1);
                *(uint32_t*)(base + 8 * HDIM) = f2h2(o2, o3);
            } else {
                float* out = (float*)outp;
                *(float2*)(out + (size_t)m * DD + n) = make_float2(o0, o1);
                *(float2*)(out + (size_t)(m + 8) * DD + n) = make_float2(o2, o3);
            }
        }
    }
}

__global__ __launch_bounds__(256, 2)
void proj_kernel(const float* __restrict__ bq, const float* __restrict__ bk,
                 const float* __restrict__ bv)
{
    const __half *X, *Wt;
    const float* bias;
    __half* out;
    const int z = blockIdx.z;
    X = g_Xh + (size_t)z * (BB * SS * DD);
    Wt = g_Wt + (size_t)z * DD * DD;
    if (z == 0)      { bias = bq; out = g_Q; }
    else if (z == 1) { bias = bk; out = g_K; }
    else             { bias = bv; out = g_V; }
    gemm_f16_body<0>(X, Wt, bias, out);
}

__global__ __launch_bounds__(256, 2)
void outproj_kernel(const float* __restrict__ bo, float* __restrict__ out)
{
    gemm_f16_body<1>(g_attn, g_Wot, bo, out);
}

// ---------------------------------------------------------------------------
// fp16 mma flash attention.
// R15 softmax rework (exact vs reference):
//  - Running max over RAW scores (no mask bias in the max path). Softmax is
//    invariant to the max offset; fp16 exps stay >= 2^-8 (no underflow).
//  - Mask applied as a packed f16 -inf bias added (one HADD2) to the f2h2
//    pack feeding ex2.f16x2 -> masked probs are EXACTLY 0. In fp32 the
//    reference's exp(s + NEG - max) is exactly 0 too (e^-1e10 underflows),
//    so denominator and numerator match bit-for-bit in effect.
//  - All-masked rows: l stays 0; ig = 1/max(l, 1e-37) and O = 0 -> output 0,
//    matching the reference's softmax*mask = 0.
//  - Max shfl reduction packed as f16x2 (hmax2): half the shfl chain.
// KV tiles of 128 keys (two 64-key halves), 3-slot cp.async ring.
// dyn smem: 3 slots x (K[128][72] + V[128][72]) = 110592 B.
// ---------------------------------------------------------------------------
__global__ __launch_bounds__(256, 2)
void attn_kernel()
{
    extern __shared__ __half hsm[];

    const int bh = blockIdx.y;
    const int b_ = bh >> 4, h_ = bh & 15;
    const int q0 = blockIdx.x * 128;

    const __half* Qp = g_Q + (size_t)bh * SS * HDIM;
    const __half* Kp = g_K + (size_t)bh * SS * HDIM;
    const __half* Vp = g_V + (size_t)bh * SS * HDIM;

    const int tid = threadIdx.x, lane = tid & 31, w = tid >> 5;
    const int g = lane >> 2, q = lane & 3;
    const int l7 = lane & 7, lb3 = (lane >> 3) & 1, lb4 = lane >> 4;
    const int row0 = 16 * w + g;

    const uint32_t sbase = smem_u32(hsm);
    auto cpaKV = [&](int t0, int slot) {
        const uint32_t kb = sbase + slot * 36864;
        #pragma unroll
        for (int i = 0; i < 4; i++) {
            const int idx = tid + 256 * i;
            const int row = idx >> 3, c8 = (idx & 7) * 8;
            const uint32_t off = (uint32_t)(row * 144 + c8 * 2);
            cpa16(kb + off,         Kp + (size_t)(t0 + row) * HDIM + c8);
            cpa16(kb + 18432 + off, Vp + (size_t)(t0 + row) * HDIM + c8);
        }
    };

    cpaKV(0, 0); CPA_COMMIT();

    // Q staged in slot 1's K region — disjoint from the in-flight slot 0
    // load; consumed before slot 1 is first written.
    __half* Qs = hsm + 18432;
    #pragma unroll
    for (int i = 0; i < 4; i++) {
        const int idx = tid + 256 * i;
        const int r = idx >> 3, c8 = (idx & 7) * 8;
        *(uint4*)&Qs[r * 72 + c8] = *(const uint4*)(Qp + (size_t)(q0 + r) * HDIM + c8);
    }
    __syncthreads();

    uint32_t qf[4][4];
    {
        const uint32_t qb = sbase + 36864;
        const int row = 16 * w + l7 + 8 * lb3;
        #pragma unroll
        for (int ks = 0; ks < 4; ks++)
            ldsm_x4(qf[ks], qb + (uint32_t)(row * 144 + (ks * 16 + 8 * lb4) * 2));
    }
    __syncthreads();   // Q hoist done; slot 1 may be overwritten

    float O[8][4];
    #pragma unroll
    for (int nf = 0; nf < 8; nf++)
        #pragma unroll
        for (int r = 0; r < 4; r++) O[nf][r] = 0.f;

    float mg = -1e30f, m8 = -1e30f, lg = 0.f, l8 = 0.f;

    const uint32_t* mrow  = g_mbits + ((size_t)b_ * SS + q0 + row0) * 32;
    const uint32_t* mrow8 = mrow + 8 * 32;

    const uint32_t klane = (uint32_t)((lb4 * 8 + l7) * 144 + lb3 * 16);
    const uint32_t vlane = (uint32_t)((lb3 * 8 + l7) * 144 + lb4 * 16);

    for (int t = 0; t < 8; t++) {
        const int slot = t % 3;
        if (t + 1 < 8) { cpaKV((t + 1) * 128, (t + 1) % 3); CPA_COMMIT(); CPA_WAIT1(); }
        else           { CPA_WAIT0(); }
        __syncthreads();

        const uint32_t kslot = sbase + slot * 36864;

        #pragma unroll
        for (int h = 0; h < 2; h++) {
            const uint32_t kbase = kslot + h * 9216;
            const uint32_t vbase = kslot + 18432 + h * 9216;

            const int wc = t * 4 + 2 * h;
            const uint64_t M0 = ((uint64_t)mrow[wc]  | ((uint64_t)mrow[wc + 1]  << 32)) >> (2 * q);
            const uint64_t M8 = ((uint64_t)mrow8[wc] | ((uint64_t)mrow8[wc + 1] << 32)) >> (2 * q);

            // ---- QK^T ----
            float s[8][4];
            #pragma unroll
            for (int nf = 0; nf < 8; nf++)
                #pragma unroll
                for (int r = 0; r < 4; r++) s[nf][r] = 0.f;

            #pragma unroll
            for (int ks = 0; ks < 4; ks++) {
                #pragma unroll
                for (int nf2 = 0; nf2 < 4; nf2++) {
                    uint32_t t4[4];
                    ldsm_x4(t4, kbase + (uint32_t)(nf2 * 2304 + ks * 32) + klane);
                    mma16(s[2 * nf2],     qf[ks], t4);
                    mma16(s[2 * nf2 + 1], qf[ks], t4 + 2);
                }
            }

            // ---- raw-score row max (no mask ops), packed f16x2 shfl ----
            float rg = -1e30f, r8 = -1e30f;
            #pragma unroll
            for (int nf = 0; nf < 8; nf++) {
                rg = fmaxf(rg, fmaxf(s[nf][0], s[nf][1]));
                r8 = fmaxf(r8, fmaxf(s[nf][2], s[nf][3]));
            }
            uint32_t pm = f2h2(rg, r8);
            pm = h2max(pm, __shfl_xor_sync(0xffffffffu, pm, 1));
            pm = h2max(pm, __shfl_xor_sync(0xffffffffu, pm, 2));
            const float2 mx = __half22float2(*reinterpret_cast<const __half2*>(&pm));

            const float mng = fmaxf(mg, mx.x * SC_LOG2);
            const float mn8 = fmaxf(m8, mx.y * SC_LOG2);
            const float ag = ex2(mg - mng), a8 = ex2(m8 - mn8);
            mg = mng; m8 = mn8;

            // ---- masked ex2 via packed -inf bias; fp32 denominator ----
            uint32_t P01[8], P23[8];
            float sg = 0.f, s8sum = 0.f;
            #pragma unroll
            for (int nf = 0; nf < 8; nf++) {
                const uint32_t b0 = (uint32_t)(M0 >> (nf * 8)) & 3u;
                const uint32_t b8 = (uint32_t)(M8 >> (nf * 8)) & 3u;
                const uint32_t bias01 = ((b0 & 1) ? 0u : 0xFC00u) | ((b0 & 2) ? 0u : 0xFC000000u);
                const uint32_t bias23 = ((b8 & 1) ? 0u : 0xFC00u) | ((b8 & 2) ? 0u : 0xFC000000u);
                const uint32_t a01 = f2h2(fmaf(s[nf][0], SC_LOG2, -mg),
                                          fmaf(s[nf][1], SC_LOG2, -mg));
                const uint32_t a23 = f2h2(fmaf(s[nf][2], SC_LOG2, -m8),
                                          fmaf(s[nf][3], SC_LOG2, -m8));
                const uint32_t e01 = h2ex2(h2add(a01, bias01));
                const uint32_t e23 = h2ex2(h2add(a23, bias23));
                const float2 f01 = __half22float2(*reinterpret_cast<const __half2*>(&e01));
                const float2 f23 = __half22float2(*reinterpret_cast<const __half2*>(&e23));
                sg    += f01.x + f01.y;
                s8sum += f23.x + f23.y;
                P01[nf] = e01;
                P23[nf] = e23;
                O[nf][0] *= ag; O[nf][1] *= ag;
                O[nf][2] *= a8; O[nf][3] *= a8;
            }
            sg    += __shfl_xor_sync(0xffffffffu, sg, 1);
            sg    += __shfl_xor_sync(0xffffffffu, sg, 2);
            s8sum += __shfl_xor_sync(0xffffffffu, s8sum, 1);
            s8sum += __shfl_xor_sync(0xffffffffu, s8sum, 2);
            lg = lg * ag + sg;
            l8 = l8 * a8 + s8sum;

            // ---- P @ V : P already packed (QK C-frag == PV A-frag) ----
            #pragma unroll
            for (int ks = 0; ks < 4; ks++) {
                uint32_t pf[4] = { P01[2 * ks], P23[2 * ks],
                                   P01[2 * ks + 1], P23[2 * ks + 1] };
                #pragma unroll
                for (int nf2 = 0; nf2 < 4; nf2++) {
                    uint32_t t4[4];
                    ldsm_x4t(t4, vbase + (uint32_t)(ks * 2304 + nf2 * 32) + vlane);
                    mma16(O[2 * nf2],     pf, t4);
                    mma16(O[2 * nf2 + 1], pf, t4 + 2);
                }
            }
        }
    }

    // ---- epilogue (all-masked rows: l==0, O==0 -> output 0) ----
    const float ig = 1.f / fmaxf(lg, 1e-37f);
    const float i8 = 1.f / fmaxf(l8, 1e-37f);
    __half* orow  = g_attn + (size_t)(b_ * SS + q0 + row0) * DD + h_ * HDIM;
    __half* orow8 = orow + 8 * DD;
    #pragma unroll
    for (int nf = 0; nf < 8; nf++) {
        const int e = nf * 8 + 2 * q;
        *(uint32_t*)(orow  + e) = f2h2(O[nf][0] * ig, O[nf][1] * ig);
        *(uint32_t*)(orow8 + e) = f2h2(O[nf][2] * i8, O[nf][3] * i8);
    }
}

// ---------------------------------------------------------------------------
extern "C" void kernel_launch(void* const* d_in, const int* in_sizes, int n_in,
                              void* d_out, int out_size)
{
    const float* q    = (const float*)d_in[0];
    const float* k    = (const float*)d_in[1];
    const float* v    = (const float*)d_in[2];
    const int*   mask = (const int*)  d_in[3];
    const float* Wq   = (const float*)d_in[4];
    const float* bq   = (const float*)d_in[5];
    const float* Wk   = (const float*)d_in[6];
    const float* bk   = (const float*)d_in[7];
    const float* Wv   = (const float*)d_in[8];
    const float* bv   = (const float*)d_in[9];
    const float* Wo   = (const float*)d_in[10];
    const float* bo   = (const float*)d_in[11];
    float* out = (float*)d_out;

    cudaFuncSetAttribute(proj_kernel,
                         cudaFuncAttributeMaxDynamicSharedMemorySize, 110592);
    cudaFuncSetAttribute(outproj_kernel,
                         cudaFuncAttributeMaxDynamicSharedMemorySize, 110592);
    cudaFuncSetAttribute(attn_kernel,
                         cudaFuncAttributeMaxDynamicSharedMemorySize, 110592);

    prepass_kernel<<<26624, 256>>>(mask, q, k, v, Wq, Wk, Wv, Wo);

    dim3 g1(8, 32, 3);                 // N/128, M/128, {Q,K,V}
    proj_kernel<<<g1, 256, 110592>>>(bq, bk, bv);

    dim3 g2(8, 64);                    // S/128 q-tiles, B*H
    attn_kernel<<<g2, 256, 110592>>>();

    dim3 g3(8, 32);                    // N/128, M/128
    outproj_kernel<<<g3, 256, 110592>>>(bo, out);
}